// round 2
// baseline (speedup 1.0000x reference)
#include <cuda_runtime.h>
#include <math.h>

#define THREADS 128
#define TILE 32

// shared-memory float offsets (all 16B aligned)
#define OFF_A    0          // 32*384 = 12288 floats: concat-x; later reused for GRU gate preacts G[32][384]
#define OFF_X1H  12288      // 32*256 = 8192: [x1 | h]; later [h_new | h]
#define OFF_GN   20480      // 32*128 = 4096: mlp1 pre-LN P; later n-gate h-part
#define OFF_WS   24576      // 32*132 = 4224: weight slab, layout Ws[k][j], row stride 132 (bank-conflict pad)
#define OFF_BIDX 28800      // 32 ints
#define SMEM_FLOATS 28832
#define SMEM_BYTES (SMEM_FLOATS * 4)

__device__ __forceinline__ float warp_sum(float v) {
#pragma unroll
    for (int o = 16; o > 0; o >>= 1) v += __shfl_xor_sync(0xffffffffu, v, o);
    return v;
}

// Load a 32-k x rows-j weight slab from gmem (row-major W[j][k], ld = ldW) into
// Ws[k*132 + j]. Wsrc must already be offset by k0.
__device__ __forceinline__ void load_slab(const float* __restrict__ Wsrc, int ldW,
                                          int rows, float* __restrict__ Ws, int t) {
    int total = rows * 32;
    for (int idx = t; idx < total; idx += THREADS) {
        int j = idx >> 5, k = idx & 31;
        Ws[k * 132 + j] = Wsrc[j * ldW + k];
    }
}

// C[e][j] += A[e][kOff..kOff+32) . Wslab ; thread owns column j, 32 edge accumulators.
__device__ __forceinline__ void gemm_slab32(const float* __restrict__ A, int ldA, int kOff,
                                            const float* __restrict__ Ws, int j,
                                            float (&acc)[32]) {
#pragma unroll
    for (int k4 = 0; k4 < 8; ++k4) {
        float w0 = Ws[(4 * k4 + 0) * 132 + j];
        float w1 = Ws[(4 * k4 + 1) * 132 + j];
        float w2 = Ws[(4 * k4 + 2) * 132 + j];
        float w3 = Ws[(4 * k4 + 3) * 132 + j];
#pragma unroll
        for (int e = 0; e < 32; ++e) {
            float4 a = *reinterpret_cast<const float4*>(A + e * ldA + kOff + 4 * k4);
            acc[e] = fmaf(a.x, w0, fmaf(a.y, w1, fmaf(a.z, w2, fmaf(a.w, w3, acc[e]))));
        }
    }
}

__global__ void __launch_bounds__(THREADS, 2)
edge_model_kernel(const float* __restrict__ src, const float* __restrict__ dest,
                  const float* __restrict__ edge_attr, const float* __restrict__ h,
                  const float* __restrict__ u, const int* __restrict__ batch,
                  const float* __restrict__ winding,
                  const float* __restrict__ Ww, const float* __restrict__ bw,
                  const float* __restrict__ gw, const float* __restrict__ betaw,
                  const float* __restrict__ W1, const float* __restrict__ b1,
                  const float* __restrict__ g1, const float* __restrict__ beta1,
                  const float* __restrict__ Wih, const float* __restrict__ Whh,
                  const float* __restrict__ bih, const float* __restrict__ bhh,
                  const float* __restrict__ Wx, const float* __restrict__ bx,
                  float* __restrict__ out_x, float* __restrict__ out_h, int E) {
    extern __shared__ float sm[];
    float* A    = sm + OFF_A;
    float* X1h  = sm + OFF_X1H;
    float* Gn   = sm + OFF_GN;
    float* Ws   = sm + OFF_WS;
    int*   bidx = (int*)(sm + OFF_BIDX);

    const int t = threadIdx.x;
    const int warp = t >> 5, lane = t & 31;
    const int eb = blockIdx.x * TILE;

    // ---------------- Phase A: loads + concat + winding MLP ----------------
    if (t < TILE) {
        int ge = eb + t;
        bidx[t] = (ge < E) ? batch[ge] : 0;
    }
    for (int idx = t; idx < TILE * 64; idx += THREADS) {
        int e = idx >> 6, f = idx & 63;
        int ge = eb + e;
        bool v = ge < E;
        A[e * 384 + f]       = v ? src[(size_t)ge * 64 + f] : 0.f;
        A[e * 384 + 64 + f]  = v ? dest[(size_t)ge * 64 + f] : 0.f;
        A[e * 384 + 128 + f] = v ? edge_attr[(size_t)ge * 64 + f] : 0.f;
    }
    for (int idx = t; idx < TILE * 128; idx += THREADS) {
        int e = idx >> 7, f = idx & 127;
        int ge = eb + e;
        X1h[e * 256 + 128 + f] = (ge < E) ? h[(size_t)ge * 128 + f] : 0.f;
    }
    __syncthreads();  // bidx ready
    for (int idx = t; idx < TILE * 64; idx += THREADS) {
        int e = idx >> 6, f = idx & 63;
        A[e * 384 + 192 + f] = u[bidx[e] * 64 + f];
    }
    // winding mlp: Linear(2->128) + LN + ReLU -> A cols 256..383
    for (int e = warp; e < TILE; e += 4) {
        int ge = eb + e;
        float wd0 = 0.f, wd1 = 0.f;
        if (ge < E) { wd0 = winding[(size_t)ge * 2]; wd1 = winding[(size_t)ge * 2 + 1]; }
        float v[4];
        float s = 0.f, s2 = 0.f;
#pragma unroll
        for (int q = 0; q < 4; ++q) {
            int jj = lane + q * 32;
            float p = fmaf(wd0, Ww[jj * 2], fmaf(wd1, Ww[jj * 2 + 1], bw[jj]));
            v[q] = p; s += p; s2 += p * p;
        }
        s = warp_sum(s); s2 = warp_sum(s2);
        float mu = s * (1.f / 128.f);
        float var = fmaxf(s2 * (1.f / 128.f) - mu * mu, 0.f);
        float rs = rsqrtf(var + 1e-5f);
#pragma unroll
        for (int q = 0; q < 4; ++q) {
            int jj = lane + q * 32;
            float y = (v[q] - mu) * rs * gw[jj] + betaw[jj];
            A[e * 384 + 256 + jj] = fmaxf(y, 0.f);
        }
    }

    // ---------------- GEMM1: P = concatX @ W1^T + b1 ----------------
    {
        float acc[32];
#pragma unroll
        for (int e = 0; e < 32; ++e) acc[e] = 0.f;
#pragma unroll 1
        for (int k0 = 0; k0 < 384; k0 += 32) {
            __syncthreads();
            load_slab(W1 + k0, 384, 128, Ws, t);
            __syncthreads();
            gemm_slab32(A, 384, k0, Ws, t, acc);
        }
        float b = b1[t];
#pragma unroll
        for (int e = 0; e < 32; ++e) Gn[e * 128 + t] = acc[e] + b;
    }
    __syncthreads();
    // LN + ReLU -> X1h[:,0:128]
    for (int e = warp; e < TILE; e += 4) {
        float v[4];
        float s = 0.f, s2 = 0.f;
#pragma unroll
        for (int q = 0; q < 4; ++q) {
            float p = Gn[e * 128 + lane + q * 32];
            v[q] = p; s += p; s2 += p * p;
        }
        s = warp_sum(s); s2 = warp_sum(s2);
        float mu = s * (1.f / 128.f);
        float var = fmaxf(s2 * (1.f / 128.f) - mu * mu, 0.f);
        float rs = rsqrtf(var + 1e-5f);
#pragma unroll
        for (int q = 0; q < 4; ++q) {
            int jj = lane + q * 32;
            float y = (v[q] - mu) * rs * g1[jj] + beta1[jj];
            X1h[e * 256 + jj] = fmaxf(y, 0.f);
        }
    }

    // ---------------- GEMM2: gate preacts; gi and gh parts ----------------
    // chunk m: output cols c = m*128 + t  (m=0 -> r, m=1 -> z, m=2 -> n)
#pragma unroll 1
    for (int m = 0; m < 3; ++m) {
        float accA[32], accB[32];  // accA: x1 @ Wih^T part (k<128); accB: h @ Whh^T part
#pragma unroll
        for (int e = 0; e < 32; ++e) { accA[e] = 0.f; accB[e] = 0.f; }
#pragma unroll 1
        for (int k0 = 0; k0 < 256; k0 += 32) {
            __syncthreads();
            const float* Wsrc = (k0 < 128) ? (Wih + m * 128 * 128 + k0)
                                           : (Whh + m * 128 * 128 + (k0 - 128));
            load_slab(Wsrc, 128, 128, Ws, t);
            __syncthreads();
            if (k0 < 128) gemm_slab32(X1h, 256, k0, Ws, t, accA);
            else          gemm_slab32(X1h, 256, k0, Ws, t, accB);
        }
        int c = m * 128 + t;
        float bi = bih[c], bh = bhh[c];
        if (m < 2) {
#pragma unroll
            for (int e = 0; e < 32; ++e) A[e * 384 + c] = accA[e] + accB[e] + bi + bh;
        } else {
            // n-gate: keep i_n and h_n separate (r multiplies only h_n)
#pragma unroll
            for (int e = 0; e < 32; ++e) {
                A[e * 384 + c]   = accA[e] + bi;
                Gn[e * 128 + t]  = accB[e] + bh;
            }
        }
    }
    __syncthreads();

    // ---------------- GRU gates + h_new ----------------
    for (int e = warp; e < TILE; e += 4) {
        int ge = eb + e;
#pragma unroll
        for (int q = 0; q < 4; ++q) {
            int jj = lane + q * 32;
            float r = 1.f / (1.f + expf(-A[e * 384 + jj]));
            float z = 1.f / (1.f + expf(-A[e * 384 + 128 + jj]));
            float n = tanhf(A[e * 384 + 256 + jj] + r * Gn[e * 128 + jj]);
            float hv = X1h[e * 256 + 128 + jj];
            float hn = (1.f - z) * n + z * hv;
            if (ge < E) out_h[(size_t)ge * 128 + jj] = hn;
            X1h[e * 256 + jj] = hn;  // h_new for GEMM3
        }
    }

    // ---------------- GEMM3: x_out = h_new @ Wx^T + bx ----------------
    {
        const int j2 = t & 63;
        const int e0 = (t >> 6) * 16;
        float acc3[16];
#pragma unroll
        for (int e = 0; e < 16; ++e) acc3[e] = 0.f;
#pragma unroll 1
        for (int k0 = 0; k0 < 128; k0 += 32) {
            __syncthreads();
            load_slab(Wx + k0, 128, 64, Ws, t);
            __syncthreads();
#pragma unroll
            for (int k4 = 0; k4 < 8; ++k4) {
                float w0 = Ws[(4 * k4 + 0) * 132 + j2];
                float w1 = Ws[(4 * k4 + 1) * 132 + j2];
                float w2 = Ws[(4 * k4 + 2) * 132 + j2];
                float w3 = Ws[(4 * k4 + 3) * 132 + j2];
#pragma unroll
                for (int e = 0; e < 16; ++e) {
                    const float* ap = X1h + (e0 + e) * 256 + k0 + 4 * k4;
                    float4 a = *reinterpret_cast<const float4*>(ap);
                    acc3[e] = fmaf(a.x, w0, fmaf(a.y, w1, fmaf(a.z, w2, fmaf(a.w, w3, acc3[e]))));
                }
            }
        }
        float b = bx[j2];
#pragma unroll
        for (int e = 0; e < 16; ++e) {
            int ge = eb + e0 + e;
            if (ge < E) out_x[(size_t)ge * 64 + j2] = acc3[e] + b;
        }
    }
}

extern "C" void kernel_launch(void* const* d_in, const int* in_sizes, int n_in,
                              void* d_out, int out_size) {
    const float* src       = (const float*)d_in[0];
    const float* dest      = (const float*)d_in[1];
    const float* edge_attr = (const float*)d_in[2];
    const float* h         = (const float*)d_in[3];
    const float* u         = (const float*)d_in[4];
    const int*   batch     = (const int*)d_in[5];
    const float* winding   = (const float*)d_in[6];
    const float* Ww        = (const float*)d_in[7];
    const float* bw        = (const float*)d_in[8];
    const float* gw        = (const float*)d_in[9];
    const float* betaw     = (const float*)d_in[10];
    const float* W1        = (const float*)d_in[11];
    const float* b1        = (const float*)d_in[12];
    const float* g1        = (const float*)d_in[13];
    const float* beta1     = (const float*)d_in[14];
    const float* Wih       = (const float*)d_in[15];
    const float* Whh       = (const float*)d_in[16];
    const float* bih       = (const float*)d_in[17];
    const float* bhh       = (const float*)d_in[18];
    const float* Wx        = (const float*)d_in[19];
    const float* bx        = (const float*)d_in[20];

    const int E = in_sizes[0] / 64;  // src is [E, 64]
    float* out_x = (float*)d_out;              // [E, 64]
    float* out_h = out_x + (size_t)E * 64;     // [E, 128]

    cudaFuncSetAttribute(edge_model_kernel,
                         cudaFuncAttributeMaxDynamicSharedMemorySize, SMEM_BYTES);

    int blocks = (E + TILE - 1) / TILE;
    edge_model_kernel<<<blocks, THREADS, SMEM_BYTES>>>(
        src, dest, edge_attr, h, u, batch, winding,
        Ww, bw, gw, betaw, W1, b1, g1, beta1,
        Wih, Whh, bih, bhh, Wx, bx, out_x, out_h, E);
}

// round 3
// speedup vs baseline: 1.9280x; 1.9280x over previous
#include <cuda_runtime.h>
#include <math.h>

#define THREADS 256
#define TILE 32

// ---- shared memory layout (floats) ----
#define OFF_A    0                    // 32 x 384 concat input
#define OFF_X1   12288                // 32 x 128: P -> x1 -> h_new
#define OFF_WS   16384                // 2 x (128*36) weight slabs (double buffered)
#define OFF_BIDX 25600                // 32 ints
#define SMEM_FLOATS 25632
#define SMEM_BYTES (SMEM_FLOATS * 4)

#define WS_STRIDE 36
#define WS_SLABF  (128 * WS_STRIDE)   // 4608 floats per slab buffer

__device__ __forceinline__ int swz(int j) { return ((j >> 2) & 7) << 2; }

__device__ __forceinline__ float warp_sum(float v) {
#pragma unroll
    for (int o = 16; o > 0; o >>= 1) v += __shfl_xor_sync(0xffffffffu, v, o);
    return v;
}

#define CP_ASYNC16(dst_sm, src_gm) \
    asm volatile("cp.async.cg.shared.global [%0], [%1], 16;\n" :: "r"(dst_sm), "l"(src_gm))
#define CP_COMMIT() asm volatile("cp.async.commit_group;\n")
#define CP_WAIT1()  asm volatile("cp.async.wait_group 1;\n")
#define CP_WAIT0()  asm volatile("cp.async.wait_group 0;\n")

// slab s -> weight source pointer (already offset to k0), leading dim, rows
__device__ __forceinline__ const float* slab_src(int s, const float* W1, const float* Wih,
                                                 const float* Whh, const float* Wx,
                                                 int& ldW, int& rows) {
    if (s < 12) { ldW = 384; rows = 128; return W1 + s * 32; }
    if (s < 36) {
        int q = s - 12; int m = q >> 3; int half = (q >> 2) & 1; int k0 = (q & 3) * 32;
        ldW = 128; rows = 128;
        const float* base = half ? Whh : Wih;
        return base + m * 128 * 128 + k0;
    }
    ldW = 128; rows = 64; return Wx + (s - 36) * 32;
}

__device__ __forceinline__ void prefetch_slab(float* wsBuf, const float* Wsrc,
                                              int ldW, int rows, int t) {
    int total = rows * 8;  // 8 quads of 4 floats per row (32 k)
    for (int idx = t; idx < total; idx += THREADS) {
        int j = idx >> 3, kk = (idx & 7) * 4;
        unsigned dst = (unsigned)__cvta_generic_to_shared(wsBuf + j * WS_STRIDE + (kk ^ swz(j)));
        CP_ASYNC16(dst, Wsrc + j * ldW + kk);
    }
}

// acc[ei][jj] += A[e][k0+kk] * Ws[j][kk]; e = warp*4+ei (broadcast), j = lane*4+jj
__device__ __forceinline__ void compute_slab_smem(const float* __restrict__ Abase, int ldA,
                                                  const float* __restrict__ Ws,
                                                  int lane, int warp, float acc[4][4]) {
    const float* Arow = Abase + warp * 4 * ldA;
    const float* Wj0 = Ws + (lane * 4 + 0) * WS_STRIDE;
    const float* Wj1 = Ws + (lane * 4 + 1) * WS_STRIDE;
    const float* Wj2 = Ws + (lane * 4 + 2) * WS_STRIDE;
    const float* Wj3 = Ws + (lane * 4 + 3) * WS_STRIDE;
    const int sw = swz(lane * 4);  // same for all 4 j in the quad (j>>2 == lane)
#pragma unroll
    for (int kk = 0; kk < 32; kk += 4) {
        int kks = kk ^ sw;
        float4 w0 = *(const float4*)(Wj0 + kks);
        float4 w1 = *(const float4*)(Wj1 + kks);
        float4 w2 = *(const float4*)(Wj2 + kks);
        float4 w3 = *(const float4*)(Wj3 + kks);
#pragma unroll
        for (int ei = 0; ei < 4; ++ei) {
            float4 a = *(const float4*)(Arow + ei * ldA + kk);
            acc[ei][0] = fmaf(a.x, w0.x, fmaf(a.y, w0.y, fmaf(a.z, w0.z, fmaf(a.w, w0.w, acc[ei][0]))));
            acc[ei][1] = fmaf(a.x, w1.x, fmaf(a.y, w1.y, fmaf(a.z, w1.z, fmaf(a.w, w1.w, acc[ei][1]))));
            acc[ei][2] = fmaf(a.x, w2.x, fmaf(a.y, w2.y, fmaf(a.z, w2.z, fmaf(a.w, w2.w, acc[ei][2]))));
            acc[ei][3] = fmaf(a.x, w3.x, fmaf(a.y, w3.y, fmaf(a.z, w3.z, fmaf(a.w, w3.w, acc[ei][3]))));
        }
    }
}

// same but A rows come from global memory (h), rows precomputed/clamped
__device__ __forceinline__ void compute_slab_gmem(const float* __restrict__ r0,
                                                  const float* __restrict__ r1,
                                                  const float* __restrict__ r2,
                                                  const float* __restrict__ r3,
                                                  const float* __restrict__ Ws,
                                                  int lane, float acc[4][4]) {
    const float* Wj0 = Ws + (lane * 4 + 0) * WS_STRIDE;
    const float* Wj1 = Ws + (lane * 4 + 1) * WS_STRIDE;
    const float* Wj2 = Ws + (lane * 4 + 2) * WS_STRIDE;
    const float* Wj3 = Ws + (lane * 4 + 3) * WS_STRIDE;
    const int sw = swz(lane * 4);
    const float* rows[4] = {r0, r1, r2, r3};
#pragma unroll
    for (int kk = 0; kk < 32; kk += 4) {
        int kks = kk ^ sw;
        float4 w0 = *(const float4*)(Wj0 + kks);
        float4 w1 = *(const float4*)(Wj1 + kks);
        float4 w2 = *(const float4*)(Wj2 + kks);
        float4 w3 = *(const float4*)(Wj3 + kks);
#pragma unroll
        for (int ei = 0; ei < 4; ++ei) {
            float4 a = __ldg((const float4*)(rows[ei] + kk));
            acc[ei][0] = fmaf(a.x, w0.x, fmaf(a.y, w0.y, fmaf(a.z, w0.z, fmaf(a.w, w0.w, acc[ei][0]))));
            acc[ei][1] = fmaf(a.x, w1.x, fmaf(a.y, w1.y, fmaf(a.z, w1.z, fmaf(a.w, w1.w, acc[ei][1]))));
            acc[ei][2] = fmaf(a.x, w2.x, fmaf(a.y, w2.y, fmaf(a.z, w2.z, fmaf(a.w, w2.w, acc[ei][2]))));
            acc[ei][3] = fmaf(a.x, w3.x, fmaf(a.y, w3.y, fmaf(a.z, w3.z, fmaf(a.w, w3.w, acc[ei][3]))));
        }
    }
}

__global__ void __launch_bounds__(THREADS, 2)
edge_model_kernel(const float* __restrict__ src, const float* __restrict__ dest,
                  const float* __restrict__ edge_attr, const float* __restrict__ h,
                  const float* __restrict__ u, const int* __restrict__ batch,
                  const float* __restrict__ winding,
                  const float* __restrict__ Ww, const float* __restrict__ bw,
                  const float* __restrict__ gw, const float* __restrict__ betaw,
                  const float* __restrict__ W1, const float* __restrict__ b1,
                  const float* __restrict__ g1, const float* __restrict__ beta1,
                  const float* __restrict__ Wih, const float* __restrict__ Whh,
                  const float* __restrict__ bih, const float* __restrict__ bhh,
                  const float* __restrict__ Wx, const float* __restrict__ bx,
                  float* __restrict__ out_x, float* __restrict__ out_h, int E) {
    extern __shared__ float sm[];
    float* A    = sm + OFF_A;
    float* X1   = sm + OFF_X1;
    float* WsB  = sm + OFF_WS;
    int*   bidx = (int*)(sm + OFF_BIDX);

    const int t = threadIdx.x;
    const int warp = t >> 5, lane = t & 31;
    const int eb = blockIdx.x * TILE;

    // ---- start weight pipeline: prefetch slab 0 ----
    {
        int ldW, rows;
        const float* ws = slab_src(0, W1, Wih, Whh, Wx, ldW, rows);
        prefetch_slab(WsB, ws, ldW, rows, t);
        CP_COMMIT();
    }

    // ---- stage A = [src|dest|ea|u[batch]|w] ----
    if (t < TILE) { int ge = eb + t; bidx[t] = (ge < E) ? batch[ge] : 0; }
    for (int idx = t; idx < TILE * 16; idx += THREADS) {
        int e = idx >> 4, q = (idx & 15) * 4;
        int ge = eb + e;
        float4 z = make_float4(0.f, 0.f, 0.f, 0.f);
        float4 a = z, b = z, c = z;
        if (ge < E) {
            a = __ldg((const float4*)(src + (size_t)ge * 64 + q));
            b = __ldg((const float4*)(dest + (size_t)ge * 64 + q));
            c = __ldg((const float4*)(edge_attr + (size_t)ge * 64 + q));
        }
        *(float4*)(A + e * 384 + q)       = a;
        *(float4*)(A + e * 384 + 64 + q)  = b;
        *(float4*)(A + e * 384 + 128 + q) = c;
    }
    __syncthreads();  // bidx ready
    for (int idx = t; idx < TILE * 16; idx += THREADS) {
        int e = idx >> 4, q = (idx & 15) * 4;
        *(float4*)(A + e * 384 + 192 + q) = __ldg((const float4*)(u + bidx[e] * 64 + q));
    }
    // winding mlp: Linear(2->128) + LN + ReLU -> A cols 256..383 (warp handles 4 edges)
#pragma unroll
    for (int ei = 0; ei < 4; ++ei) {
        int e = warp * 4 + ei;
        int ge = eb + e;
        float wd0 = 0.f, wd1 = 0.f;
        if (ge < E) { wd0 = winding[(size_t)ge * 2]; wd1 = winding[(size_t)ge * 2 + 1]; }
        float v[4], s = 0.f, s2 = 0.f;
#pragma unroll
        for (int q = 0; q < 4; ++q) {
            int jj = lane + q * 32;
            float p = fmaf(wd0, Ww[jj * 2], fmaf(wd1, Ww[jj * 2 + 1], bw[jj]));
            v[q] = p; s += p; s2 += p * p;
        }
        s = warp_sum(s); s2 = warp_sum(s2);
        float mu = s * (1.f / 128.f);
        float var = fmaxf(s2 * (1.f / 128.f) - mu * mu, 0.f);
        float rs = rsqrtf(var + 1e-5f);
#pragma unroll
        for (int q = 0; q < 4; ++q) {
            int jj = lane + q * 32;
            A[e * 384 + 256 + jj] = fmaxf((v[q] - mu) * rs * gw[jj] + betaw[jj], 0.f);
        }
    }

    // ---------------- GEMM1: P = A @ W1^T (12 slabs) ----------------
    float accP[4][4];
#pragma unroll
    for (int a_ = 0; a_ < 4; ++a_)
#pragma unroll
        for (int b_ = 0; b_ < 4; ++b_) accP[a_][b_] = 0.f;
#pragma unroll 1
    for (int s = 0; s < 12; ++s) {
        { int ldW, rows; const float* ws = slab_src(s + 1, W1, Wih, Whh, Wx, ldW, rows);
          prefetch_slab(WsB + ((s + 1) & 1) * WS_SLABF, ws, ldW, rows, t); CP_COMMIT(); }
        CP_WAIT1();
        __syncthreads();
        compute_slab_smem(A + s * 32, 384, WsB + (s & 1) * WS_SLABF, lane, warp, accP);
        __syncthreads();
    }
    // store P + b1 -> X1
    {
        float4 bq = __ldg((const float4*)(b1 + lane * 4));
#pragma unroll
        for (int ei = 0; ei < 4; ++ei) {
            float4 p = make_float4(accP[ei][0] + bq.x, accP[ei][1] + bq.y,
                                   accP[ei][2] + bq.z, accP[ei][3] + bq.w);
            *(float4*)(X1 + (warp * 4 + ei) * 128 + lane * 4) = p;
        }
    }
    __syncthreads();
    // LN + ReLU in place
#pragma unroll
    for (int ei = 0; ei < 4; ++ei) {
        int e = warp * 4 + ei;
        float v[4], s = 0.f, s2 = 0.f;
#pragma unroll
        for (int q = 0; q < 4; ++q) {
            float p = X1[e * 128 + lane + q * 32];
            v[q] = p; s += p; s2 += p * p;
        }
        s = warp_sum(s); s2 = warp_sum(s2);
        float mu = s * (1.f / 128.f);
        float var = fmaxf(s2 * (1.f / 128.f) - mu * mu, 0.f);
        float rs = rsqrtf(var + 1e-5f);
#pragma unroll
        for (int q = 0; q < 4; ++q) {
            int jj = lane + q * 32;
            X1[e * 128 + jj] = fmaxf((v[q] - mu) * rs * g1[jj] + beta1[jj], 0.f);
        }
    }
    __syncthreads();

    // h row pointers (clamped) for gmem operand
    const float* hr[4];
#pragma unroll
    for (int ei = 0; ei < 4; ++ei) {
        int ge = eb + warp * 4 + ei;
        if (ge > E - 1) ge = E - 1;
        hr[ei] = h + (size_t)ge * 128;
    }

    // ---------------- GEMM2: 3 gate chunks, gates kept in registers ----------------
    float rg[4][4], zg[4][4];
#pragma unroll 1
    for (int m = 0; m < 3; ++m) {
        float accA[4][4], accB[4][4];
#pragma unroll
        for (int a_ = 0; a_ < 4; ++a_)
#pragma unroll
            for (int b_ = 0; b_ < 4; ++b_) { accA[a_][b_] = 0.f; accB[a_][b_] = 0.f; }
#pragma unroll 1
        for (int ss = 0; ss < 8; ++ss) {
            int s = 12 + m * 8 + ss;
            { int ldW, rows; const float* ws = slab_src(s + 1, W1, Wih, Whh, Wx, ldW, rows);
              prefetch_slab(WsB + ((s + 1) & 1) * WS_SLABF, ws, ldW, rows, t); CP_COMMIT(); }
            CP_WAIT1();
            __syncthreads();
            const float* Ws = WsB + (s & 1) * WS_SLABF;
            if (ss < 4) compute_slab_smem(X1 + ss * 32, 128, Ws, lane, warp, accA);
            else {
                int k0 = (ss - 4) * 32;
                compute_slab_gmem(hr[0] + k0, hr[1] + k0, hr[2] + k0, hr[3] + k0,
                                  Ws, lane, accB);
            }
            __syncthreads();
        }
        float4 biq = __ldg((const float4*)(bih + m * 128 + lane * 4));
        float4 bhq = __ldg((const float4*)(bhh + m * 128 + lane * 4));
        if (m == 0) {
#pragma unroll
            for (int ei = 0; ei < 4; ++ei) {
                rg[ei][0] = 1.f / (1.f + expf(-(accA[ei][0] + accB[ei][0] + biq.x + bhq.x)));
                rg[ei][1] = 1.f / (1.f + expf(-(accA[ei][1] + accB[ei][1] + biq.y + bhq.y)));
                rg[ei][2] = 1.f / (1.f + expf(-(accA[ei][2] + accB[ei][2] + biq.z + bhq.z)));
                rg[ei][3] = 1.f / (1.f + expf(-(accA[ei][3] + accB[ei][3] + biq.w + bhq.w)));
            }
        } else if (m == 1) {
#pragma unroll
            for (int ei = 0; ei < 4; ++ei) {
                zg[ei][0] = 1.f / (1.f + expf(-(accA[ei][0] + accB[ei][0] + biq.x + bhq.x)));
                zg[ei][1] = 1.f / (1.f + expf(-(accA[ei][1] + accB[ei][1] + biq.y + bhq.y)));
                zg[ei][2] = 1.f / (1.f + expf(-(accA[ei][2] + accB[ei][2] + biq.z + bhq.z)));
                zg[ei][3] = 1.f / (1.f + expf(-(accA[ei][3] + accB[ei][3] + biq.w + bhq.w)));
            }
        } else {
            // n = tanh(i_n + r * h_n); h_new = (1-z)*n + z*h
#pragma unroll
            for (int ei = 0; ei < 4; ++ei) {
                int ge = eb + warp * 4 + ei;
                float4 hv = __ldg((const float4*)(hr[ei] + lane * 4));
                float n0 = tanhf(accA[ei][0] + biq.x + rg[ei][0] * (accB[ei][0] + bhq.x));
                float n1 = tanhf(accA[ei][1] + biq.y + rg[ei][1] * (accB[ei][1] + bhq.y));
                float n2 = tanhf(accA[ei][2] + biq.z + rg[ei][2] * (accB[ei][2] + bhq.z));
                float n3 = tanhf(accA[ei][3] + biq.w + rg[ei][3] * (accB[ei][3] + bhq.w));
                float4 hn;
                hn.x = (1.f - zg[ei][0]) * n0 + zg[ei][0] * hv.x;
                hn.y = (1.f - zg[ei][1]) * n1 + zg[ei][1] * hv.y;
                hn.z = (1.f - zg[ei][2]) * n2 + zg[ei][2] * hv.z;
                hn.w = (1.f - zg[ei][3]) * n3 + zg[ei][3] * hv.w;
                if (ge < E) *(float4*)(out_h + (size_t)ge * 128 + lane * 4) = hn;
                *(float4*)(X1 + (warp * 4 + ei) * 128 + lane * 4) = hn;  // for GEMM3
            }
        }
    }
    __syncthreads();

    // ---------------- GEMM3: x_out = h_new @ Wx^T (4 slabs, 4e x 2j tiles) ----------------
    {
        float acc3[4][2];
#pragma unroll
        for (int a_ = 0; a_ < 4; ++a_) { acc3[a_][0] = 0.f; acc3[a_][1] = 0.f; }
        const int j0 = lane * 2, j1 = lane * 2 + 1;
        const int sw0 = swz(j0), sw1 = swz(j1);
#pragma unroll 1
        for (int ss = 0; ss < 4; ++ss) {
            int s = 36 + ss;
            if (s + 1 < 40) {
                int ldW, rows; const float* ws = slab_src(s + 1, W1, Wih, Whh, Wx, ldW, rows);
                prefetch_slab(WsB + ((s + 1) & 1) * WS_SLABF, ws, ldW, rows, t); CP_COMMIT();
                CP_WAIT1();
            } else {
                CP_WAIT0();
            }
            __syncthreads();
            const float* Ws = WsB + (s & 1) * WS_SLABF;
            const float* Arow = X1 + warp * 4 * 128 + ss * 32;
#pragma unroll
            for (int kk = 0; kk < 32; kk += 4) {
                float4 w0 = *(const float4*)(Ws + j0 * WS_STRIDE + (kk ^ sw0));
                float4 w1 = *(const float4*)(Ws + j1 * WS_STRIDE + (kk ^ sw1));
#pragma unroll
                for (int ei = 0; ei < 4; ++ei) {
                    float4 a = *(const float4*)(Arow + ei * 128 + kk);
                    acc3[ei][0] = fmaf(a.x, w0.x, fmaf(a.y, w0.y, fmaf(a.z, w0.z, fmaf(a.w, w0.w, acc3[ei][0]))));
                    acc3[ei][1] = fmaf(a.x, w1.x, fmaf(a.y, w1.y, fmaf(a.z, w1.z, fmaf(a.w, w1.w, acc3[ei][1]))));
                }
            }
            __syncthreads();
        }
        float bx0 = __ldg(bx + j0), bx1 = __ldg(bx + j1);
#pragma unroll
        for (int ei = 0; ei < 4; ++ei) {
            int ge = eb + warp * 4 + ei;
            if (ge < E) {
                float2 o = make_float2(acc3[ei][0] + bx0, acc3[ei][1] + bx1);
                *(float2*)(out_x + (size_t)ge * 64 + j0) = o;
            }
        }
    }
}

extern "C" void kernel_launch(void* const* d_in, const int* in_sizes, int n_in,
                              void* d_out, int out_size) {
    const float* src       = (const float*)d_in[0];
    const float* dest      = (const float*)d_in[1];
    const float* edge_attr = (const float*)d_in[2];
    const float* h         = (const float*)d_in[3];
    const float* u         = (const float*)d_in[4];
    const int*   batch     = (const int*)d_in[5];
    const float* winding   = (const float*)d_in[6];
    const float* Ww        = (const float*)d_in[7];
    const float* bw        = (const float*)d_in[8];
    const float* gw        = (const float*)d_in[9];
    const float* betaw     = (const float*)d_in[10];
    const float* W1        = (const float*)d_in[11];
    const float* b1        = (const float*)d_in[12];
    const float* g1        = (const float*)d_in[13];
    const float* beta1     = (const float*)d_in[14];
    const float* Wih       = (const float*)d_in[15];
    const float* Whh       = (const float*)d_in[16];
    const float* bih       = (const float*)d_in[17];
    const float* bhh       = (const float*)d_in[18];
    const float* Wx        = (const float*)d_in[19];
    const float* bx        = (const float*)d_in[20];

    const int E = in_sizes[0] / 64;  // src is [E, 64]
    float* out_x = (float*)d_out;              // [E, 64]
    float* out_h = out_x + (size_t)E * 64;     // [E, 128]

    cudaFuncSetAttribute(edge_model_kernel,
                         cudaFuncAttributeMaxDynamicSharedMemorySize, SMEM_BYTES);

    int blocks = (E + TILE - 1) / TILE;
    edge_model_kernel<<<blocks, THREADS, SMEM_BYTES>>>(
        src, dest, edge_attr, h, u, batch, winding,
        Ww, bw, gw, betaw, W1, b1, g1, beta1,
        Wih, Whh, bih, bhh, Wx, bx, out_x, out_h, E);
}

// round 6
// speedup vs baseline: 2.0470x; 1.0617x over previous
#include <cuda_runtime.h>
#include <math.h>

#define THREADS 256
#define TILE 32

typedef unsigned long long ull;

// ---- shared memory layout (floats) ----
#define OFF_A    0                    // 32 x 384 concat input; later r/z gate buffers
#define OFF_X1   12288                // 32 x 128: P -> x1 -> h_new
#define OFF_WS   16384                // 2 x (128*36) weight slabs (double buffered)
#define OFF_BIDX 25600                // 32 ints
#define SMEM_FLOATS 25632
#define SMEM_BYTES (SMEM_FLOATS * 4)

#define WS_STRIDE 36
#define WS_SLABF  (128 * WS_STRIDE)   // 4608 floats per slab buffer

__device__ __forceinline__ int swz(int j) { return ((j >> 2) & 7) << 2; }

__device__ __forceinline__ float warp_sum(float v) {
#pragma unroll
    for (int o = 16; o > 0; o >>= 1) v += __shfl_xor_sync(0xffffffffu, v, o);
    return v;
}

// packed dual FMA: d.{lo,hi} += a.{lo,hi} * b.{lo,hi}
__device__ __forceinline__ void ffma2(ull& d, ull a, ull b) {
    asm("fma.rn.f32x2 %0, %1, %2, %0;" : "+l"(d) : "l"(a), "l"(b));
}
__device__ __forceinline__ float red2(ull v) {
    float lo = __uint_as_float((unsigned)(v & 0xffffffffull));
    float hi = __uint_as_float((unsigned)(v >> 32));
    return lo + hi;
}

#define CP_ASYNC16(dst_sm, src_gm) \
    asm volatile("cp.async.cg.shared.global [%0], [%1], 16;\n" :: "r"(dst_sm), "l"(src_gm))
#define CP_COMMIT() asm volatile("cp.async.commit_group;\n")
#define CP_WAIT1()  asm volatile("cp.async.wait_group 1;\n")
#define CP_WAIT0()  asm volatile("cp.async.wait_group 0;\n")

// slab s -> weight source pointer (already offset to k0), leading dim, rows
__device__ __forceinline__ const float* slab_src(int s, const float* W1, const float* Wih,
                                                 const float* Whh, const float* Wx,
                                                 int& ldW, int& rows) {
    if (s < 12) { ldW = 384; rows = 128; return W1 + s * 32; }
    if (s < 36) {
        int q = s - 12; int m = q >> 3; int half = (q >> 2) & 1; int k0 = (q & 3) * 32;
        ldW = 128; rows = 128;
        const float* base = half ? Whh : Wih;
        return base + m * 128 * 128 + k0;
    }
    ldW = 128; rows = 64; return Wx + (s - 36) * 32;
}

__device__ __forceinline__ void prefetch_slab(float* wsBuf, const float* Wsrc,
                                              int ldW, int rows, int t) {
    int total = rows * 8;  // 8 quads of 4 floats per row (32 k)
    for (int idx = t; idx < total; idx += THREADS) {
        int j = idx >> 3, kk = (idx & 7) * 4;
        unsigned dst = (unsigned)__cvta_generic_to_shared(wsBuf + j * WS_STRIDE + (kk ^ swz(j)));
        CP_ASYNC16(dst, Wsrc + j * ldW + kk);
    }
}

// acc[ei][jj] packed over k-pairs; e = warp*4+ei (broadcast A), j = lane*4+jj
__device__ __forceinline__ void compute_slab_smem(const float* __restrict__ Abase, int ldA,
                                                  const float* __restrict__ Ws,
                                                  int lane, int warp, ull acc[4][4]) {
    const float* Arow = Abase + warp * 4 * ldA;
    const float* Wj0 = Ws + (lane * 4 + 0) * WS_STRIDE;
    const float* Wj1 = Ws + (lane * 4 + 1) * WS_STRIDE;
    const float* Wj2 = Ws + (lane * 4 + 2) * WS_STRIDE;
    const float* Wj3 = Ws + (lane * 4 + 3) * WS_STRIDE;
    const int sw = swz(lane * 4);  // same for all 4 j in the quad
#pragma unroll
    for (int kk = 0; kk < 32; kk += 4) {
        int kks = kk ^ sw;
        ulonglong2 w0 = *(const ulonglong2*)(Wj0 + kks);
        ulonglong2 w1 = *(const ulonglong2*)(Wj1 + kks);
        ulonglong2 w2 = *(const ulonglong2*)(Wj2 + kks);
        ulonglong2 w3 = *(const ulonglong2*)(Wj3 + kks);
#pragma unroll
        for (int ei = 0; ei < 4; ++ei) {
            ulonglong2 a = *(const ulonglong2*)(Arow + ei * ldA + kk);
            ffma2(acc[ei][0], a.x, w0.x); ffma2(acc[ei][0], a.y, w0.y);
            ffma2(acc[ei][1], a.x, w1.x); ffma2(acc[ei][1], a.y, w1.y);
            ffma2(acc[ei][2], a.x, w2.x); ffma2(acc[ei][2], a.y, w2.y);
            ffma2(acc[ei][3], a.x, w3.x); ffma2(acc[ei][3], a.y, w3.y);
        }
    }
}

// same but A rows come from global memory (h), row pointers precomputed/clamped
__device__ __forceinline__ void compute_slab_gmem(const float* __restrict__ r0,
                                                  const float* __restrict__ r1,
                                                  const float* __restrict__ r2,
                                                  const float* __restrict__ r3,
                                                  const float* __restrict__ Ws,
                                                  int lane, ull acc[4][4]) {
    const float* Wj0 = Ws + (lane * 4 + 0) * WS_STRIDE;
    const float* Wj1 = Ws + (lane * 4 + 1) * WS_STRIDE;
    const float* Wj2 = Ws + (lane * 4 + 2) * WS_STRIDE;
    const float* Wj3 = Ws + (lane * 4 + 3) * WS_STRIDE;
    const int sw = swz(lane * 4);
    const float* rows[4] = {r0, r1, r2, r3};
#pragma unroll
    for (int kk = 0; kk < 32; kk += 4) {
        int kks = kk ^ sw;
        ulonglong2 w0 = *(const ulonglong2*)(Wj0 + kks);
        ulonglong2 w1 = *(const ulonglong2*)(Wj1 + kks);
        ulonglong2 w2 = *(const ulonglong2*)(Wj2 + kks);
        ulonglong2 w3 = *(const ulonglong2*)(Wj3 + kks);
#pragma unroll
        for (int ei = 0; ei < 4; ++ei) {
            ulonglong2 a = *(const ulonglong2*)(rows[ei] + kk);
            ffma2(acc[ei][0], a.x, w0.x); ffma2(acc[ei][0], a.y, w0.y);
            ffma2(acc[ei][1], a.x, w1.x); ffma2(acc[ei][1], a.y, w1.y);
            ffma2(acc[ei][2], a.x, w2.x); ffma2(acc[ei][2], a.y, w2.y);
            ffma2(acc[ei][3], a.x, w3.x); ffma2(acc[ei][3], a.y, w3.y);
        }
    }
}

__global__ void __launch_bounds__(THREADS, 2)
edge_model_kernel(const float* __restrict__ src, const float* __restrict__ dest,
                  const float* __restrict__ edge_attr, const float* __restrict__ h,
                  const float* __restrict__ u, const int* __restrict__ batch,
                  const float* __restrict__ winding,
                  const float* __restrict__ Ww, const float* __restrict__ bw,
                  const float* __restrict__ gw, const float* __restrict__ betaw,
                  const float* __restrict__ W1, const float* __restrict__ b1,
                  const float* __restrict__ g1, const float* __restrict__ beta1,
                  const float* __restrict__ Wih, const float* __restrict__ Whh,
                  const float* __restrict__ bih, const float* __restrict__ bhh,
                  const float* __restrict__ Wx, const float* __restrict__ bx,
                  float* __restrict__ out_x, float* __restrict__ out_h, int E) {
    extern __shared__ float sm[];
    float* A    = sm + OFF_A;
    float* X1   = sm + OFF_X1;
    float* WsB  = sm + OFF_WS;
    int*   bidx = (int*)(sm + OFF_BIDX);
    float* Rbuf = A;            // r-gate values, [e][j] (A region is free after GEMM1)
    float* Zbuf = A + 4096;     // z-gate values

    const int t = threadIdx.x;
    const int warp = t >> 5, lane = t & 31;
    const int eb = blockIdx.x * TILE;

    // ---- start weight pipeline: prefetch slab 0 ----
    {
        int ldW, rows;
        const float* ws = slab_src(0, W1, Wih, Whh, Wx, ldW, rows);
        prefetch_slab(WsB, ws, ldW, rows, t);
        CP_COMMIT();
    }

    // ---- stage A = [src|dest|ea|u[batch]|w] ----
    if (t < TILE) { int ge = eb + t; bidx[t] = (ge < E) ? batch[ge] : 0; }
    for (int idx = t; idx < TILE * 16; idx += THREADS) {
        int e = idx >> 4, q = (idx & 15) * 4;
        int ge = eb + e;
        float4 z = make_float4(0.f, 0.f, 0.f, 0.f);
        float4 a = z, b = z, c = z;
        if (ge < E) {
            a = __ldg((const float4*)(src + (size_t)ge * 64 + q));
            b = __ldg((const float4*)(dest + (size_t)ge * 64 + q));
            c = __ldg((const float4*)(edge_attr + (size_t)ge * 64 + q));
        }
        *(float4*)(A + e * 384 + q)       = a;
        *(float4*)(A + e * 384 + 64 + q)  = b;
        *(float4*)(A + e * 384 + 128 + q) = c;
    }
    __syncthreads();  // bidx ready
    for (int idx = t; idx < TILE * 16; idx += THREADS) {
        int e = idx >> 4, q = (idx & 15) * 4;
        *(float4*)(A + e * 384 + 192 + q) = __ldg((const float4*)(u + bidx[e] * 64 + q));
    }
    // winding mlp: Linear(2->128) + LN + ReLU -> A cols 256..383 (warp handles 4 edges)
#pragma unroll
    for (int ei = 0; ei < 4; ++ei) {
        int e = warp * 4 + ei;
        int ge = eb + e;
        float wd0 = 0.f, wd1 = 0.f;
        if (ge < E) { wd0 = winding[(size_t)ge * 2]; wd1 = winding[(size_t)ge * 2 + 1]; }
        float v[4], s = 0.f, s2 = 0.f;
#pragma unroll
        for (int q = 0; q < 4; ++q) {
            int jj = lane + q * 32;
            float p = fmaf(wd0, Ww[jj * 2], fmaf(wd1, Ww[jj * 2 + 1], bw[jj]));
            v[q] = p; s += p; s2 += p * p;
        }
        s = warp_sum(s); s2 = warp_sum(s2);
        float mu = s * (1.f / 128.f);
        float var = fmaxf(s2 * (1.f / 128.f) - mu * mu, 0.f);
        float rs = rsqrtf(var + 1e-5f);
#pragma unroll
        for (int q = 0; q < 4; ++q) {
            int jj = lane + q * 32;
            A[e * 384 + 256 + jj] = fmaxf((v[q] - mu) * rs * gw[jj] + betaw[jj], 0.f);
        }
    }

    // ---------------- GEMM1: P = A @ W1^T (12 slabs) ----------------
    {
        ull accP[4][4];
#pragma unroll
        for (int a_ = 0; a_ < 4; ++a_)
#pragma unroll
            for (int b_ = 0; b_ < 4; ++b_) accP[a_][b_] = 0ull;
#pragma unroll 1
        for (int s = 0; s < 12; ++s) {
            { int ldW, rows; const float* ws = slab_src(s + 1, W1, Wih, Whh, Wx, ldW, rows);
              prefetch_slab(WsB + ((s + 1) & 1) * WS_SLABF, ws, ldW, rows, t); CP_COMMIT(); }
            CP_WAIT1();
            __syncthreads();
            compute_slab_smem(A + s * 32, 384, WsB + (s & 1) * WS_SLABF, lane, warp, accP);
            __syncthreads();
        }
        float4 bq = __ldg((const float4*)(b1 + lane * 4));
#pragma unroll
        for (int ei = 0; ei < 4; ++ei) {
            float4 p = make_float4(red2(accP[ei][0]) + bq.x, red2(accP[ei][1]) + bq.y,
                                   red2(accP[ei][2]) + bq.z, red2(accP[ei][3]) + bq.w);
            *(float4*)(X1 + (warp * 4 + ei) * 128 + lane * 4) = p;
        }
    }
    __syncthreads();
    // LN + ReLU in place
#pragma unroll
    for (int ei = 0; ei < 4; ++ei) {
        int e = warp * 4 + ei;
        float v[4], s = 0.f, s2 = 0.f;
#pragma unroll
        for (int q = 0; q < 4; ++q) {
            float p = X1[e * 128 + lane + q * 32];
            v[q] = p; s += p; s2 += p * p;
        }
        s = warp_sum(s); s2 = warp_sum(s2);
        float mu = s * (1.f / 128.f);
        float var = fmaxf(s2 * (1.f / 128.f) - mu * mu, 0.f);
        float rs = rsqrtf(var + 1e-5f);
#pragma unroll
        for (int q = 0; q < 4; ++q) {
            int jj = lane + q * 32;
            X1[e * 128 + jj] = fmaxf((v[q] - mu) * rs * g1[jj] + beta1[jj], 0.f);
        }
    }
    __syncthreads();

    // h row pointers (clamped) for gmem operand
    const float* hr[4];
#pragma unroll
    for (int ei = 0; ei < 4; ++ei) {
        int ge = eb + warp * 4 + ei;
        if (ge > E - 1) ge = E - 1;
        hr[ei] = h + (size_t)ge * 128;
    }

    // ---------------- GEMM2: r and z gates (combined accumulator) ----------------
#pragma unroll 1
    for (int m = 0; m < 2; ++m) {
        ull acc[4][4];
#pragma unroll
        for (int a_ = 0; a_ < 4; ++a_)
#pragma unroll
            for (int b_ = 0; b_ < 4; ++b_) acc[a_][b_] = 0ull;
#pragma unroll 1
        for (int ss = 0; ss < 8; ++ss) {
            int s = 12 + m * 8 + ss;
            { int ldW, rows; const float* ws = slab_src(s + 1, W1, Wih, Whh, Wx, ldW, rows);
              prefetch_slab(WsB + ((s + 1) & 1) * WS_SLABF, ws, ldW, rows, t); CP_COMMIT(); }
            CP_WAIT1();
            __syncthreads();
            const float* Ws = WsB + (s & 1) * WS_SLABF;
            if (ss < 4) compute_slab_smem(X1 + ss * 32, 128, Ws, lane, warp, acc);
            else {
                int k0 = (ss - 4) * 32;
                compute_slab_gmem(hr[0] + k0, hr[1] + k0, hr[2] + k0, hr[3] + k0,
                                  Ws, lane, acc);
            }
            __syncthreads();
        }
        float4 biq = __ldg((const float4*)(bih + m * 128 + lane * 4));
        float4 bhq = __ldg((const float4*)(bhh + m * 128 + lane * 4));
        float* Gbuf = (m == 0) ? Rbuf : Zbuf;
#pragma unroll
        for (int ei = 0; ei < 4; ++ei) {
            float4 g;
            g.x = 1.f / (1.f + expf(-(red2(acc[ei][0]) + biq.x + bhq.x)));
            g.y = 1.f / (1.f + expf(-(red2(acc[ei][1]) + biq.y + bhq.y)));
            g.z = 1.f / (1.f + expf(-(red2(acc[ei][2]) + biq.z + bhq.z)));
            g.w = 1.f / (1.f + expf(-(red2(acc[ei][3]) + biq.w + bhq.w)));
            *(float4*)(Gbuf + (warp * 4 + ei) * 128 + lane * 4) = g;
        }
    }

    // ---------------- GEMM2: n gate (separate i/h accumulators) ----------------
    {
        ull accA[4][4], accB[4][4];
#pragma unroll
        for (int a_ = 0; a_ < 4; ++a_)
#pragma unroll
            for (int b_ = 0; b_ < 4; ++b_) { accA[a_][b_] = 0ull; accB[a_][b_] = 0ull; }
#pragma unroll 1
        for (int ss = 0; ss < 8; ++ss) {
            int s = 28 + ss;
            { int ldW, rows; const float* ws = slab_src(s + 1, W1, Wih, Whh, Wx, ldW, rows);
              prefetch_slab(WsB + ((s + 1) & 1) * WS_SLABF, ws, ldW, rows, t); CP_COMMIT(); }
            CP_WAIT1();
            __syncthreads();
            const float* Ws = WsB + (s & 1) * WS_SLABF;
            if (ss < 4) compute_slab_smem(X1 + ss * 32, 128, Ws, lane, warp, accA);
            else {
                int k0 = (ss - 4) * 32;
                compute_slab_gmem(hr[0] + k0, hr[1] + k0, hr[2] + k0, hr[3] + k0,
                                  Ws, lane, accB);
            }
            __syncthreads();
        }
        float4 biq = __ldg((const float4*)(bih + 256 + lane * 4));
        float4 bhq = __ldg((const float4*)(bhh + 256 + lane * 4));
#pragma unroll
        for (int ei = 0; ei < 4; ++ei) {
            int ge = eb + warp * 4 + ei;
            float4 hv = *(const float4*)(hr[ei] + lane * 4);
            float4 rv = *(const float4*)(Rbuf + (warp * 4 + ei) * 128 + lane * 4);
            float4 zv = *(const float4*)(Zbuf + (warp * 4 + ei) * 128 + lane * 4);
            float n0 = tanhf(red2(accA[ei][0]) + biq.x + rv.x * (red2(accB[ei][0]) + bhq.x));
            float n1 = tanhf(red2(accA[ei][1]) + biq.y + rv.y * (red2(accB[ei][1]) + bhq.y));
            float n2 = tanhf(red2(accA[ei][2]) + biq.z + rv.z * (red2(accB[ei][2]) + bhq.z));
            float n3 = tanhf(red2(accA[ei][3]) + biq.w + rv.w * (red2(accB[ei][3]) + bhq.w));
            float4 hn;
            hn.x = (1.f - zv.x) * n0 + zv.x * hv.x;
            hn.y = (1.f - zv.y) * n1 + zv.y * hv.y;
            hn.z = (1.f - zv.z) * n2 + zv.z * hv.z;
            hn.w = (1.f - zv.w) * n3 + zv.w * hv.w;
            if (ge < E) *(float4*)(out_h + (size_t)ge * 128 + lane * 4) = hn;
            *(float4*)(X1 + (warp * 4 + ei) * 128 + lane * 4) = hn;  // for GEMM3
        }
    }
    __syncthreads();

    // ---------------- GEMM3: x_out = h_new @ Wx^T (4 slabs, 4e x 2j tiles) ----------------
    {
        ull acc3[4][2];
#pragma unroll
        for (int a_ = 0; a_ < 4; ++a_) { acc3[a_][0] = 0ull; acc3[a_][1] = 0ull; }
        const int j0 = lane * 2, j1 = lane * 2 + 1;
        const int sw0 = swz(j0), sw1 = swz(j1);
#pragma unroll 1
        for (int ss = 0; ss < 4; ++ss) {
            int s = 36 + ss;
            if (s + 1 < 40) {
                int ldW, rows; const float* ws = slab_src(s + 1, W1, Wih, Whh, Wx, ldW, rows);
                prefetch_slab(WsB + ((s + 1) & 1) * WS_SLABF, ws, ldW, rows, t); CP_COMMIT();
                CP_WAIT1();
            } else {
                CP_WAIT0();
            }
            __syncthreads();
            const float* Ws = WsB + (s & 1) * WS_SLABF;
            const float* Arow = X1 + warp * 4 * 128 + ss * 32;
#pragma unroll
            for (int kk = 0; kk < 32; kk += 4) {
                ulonglong2 w0 = *(const ulonglong2*)(Ws + j0 * WS_STRIDE + (kk ^ sw0));
                ulonglong2 w1 = *(const ulonglong2*)(Ws + j1 * WS_STRIDE + (kk ^ sw1));
#pragma unroll
                for (int ei = 0; ei < 4; ++ei) {
                    ulonglong2 a = *(const ulonglong2*)(Arow + ei * 128 + kk);
                    ffma2(acc3[ei][0], a.x, w0.x); ffma2(acc3[ei][0], a.y, w0.y);
                    ffma2(acc3[ei][1], a.x, w1.x); ffma2(acc3[ei][1], a.y, w1.y);
                }
            }
            __syncthreads();
        }
        float bx0 = __ldg(bx + j0), bx1 = __ldg(bx + j1);
#pragma unroll
        for (int ei = 0; ei < 4; ++ei) {
            int ge = eb + warp * 4 + ei;
            if (ge < E) {
                float2 o = make_float2(red2(acc3[ei][0]) + bx0, red2(acc3[ei][1]) + bx1);
                *(float2*)(out_x + (size_t)ge * 64 + j0) = o;
            }
        }
    }
}

extern "C" void kernel_launch(void* const* d_in, const int* in_sizes, int n_in,
                              void* d_out, int out_size) {
    const float* src       = (const float*)d_in[0];
    const float* dest      = (const float*)d_in[1];
    const float* edge_attr = (const float*)d_in[2];
    const float* h         = (const float*)d_in[3];
    const float* u         = (const float*)d_in[4];
    const int*   batch     = (const int*)d_in[5];
    const float* winding   = (const float*)d_in[6];
    const float* Ww        = (const float*)d_in[7];
    const float* bw        = (const float*)d_in[8];
    const float* gw        = (const float*)d_in[9];
    const float* betaw     = (const float*)d_in[10];
    const float* W1        = (const float*)d_in[11];
    const float* b1        = (const float*)d_in[12];
    const float* g1        = (const float*)d_in[13];
    const float* beta1     = (const float*)d_in[14];
    const float* Wih       = (const float*)d_in[15];
    const float* Whh       = (const float*)d_in[16];
    const float* bih       = (const float*)d_in[17];
    const float* bhh       = (const float*)d_in[18];
    const float* Wx        = (const float*)d_in[19];
    const float* bx        = (const float*)d_in[20];

    const int E = in_sizes[0] / 64;  // src is [E, 64]
    float* out_x = (float*)d_out;              // [E, 64]
    float* out_h = out_x + (size_t)E * 64;     // [E, 128]

    cudaFuncSetAttribute(edge_model_kernel,
                         cudaFuncAttributeMaxDynamicSharedMemorySize, SMEM_BYTES);

    int blocks = (E + TILE - 1) / TILE;
    edge_model_kernel<<<blocks, THREADS, SMEM_BYTES>>>(
        src, dest, edge_attr, h, u, batch, winding,
        Ww, bw, gw, betaw, W1, b1, g1, beta1,
        Wih, Whh, bih, bhh, Wx, bx, out_x, out_h, E);
}

// round 8
// speedup vs baseline: 2.2160x; 1.0826x over previous
#include <cuda_runtime.h>
#include <math.h>

#define THREADS 256
#define TILE 64

typedef unsigned long long ull;

// ---- shared memory layout (floats) ----
#define OFF_AW   0        // 64x128: winding-mlp out -> later r-gate plane
#define OFF_X1   8192     // 64x128: x1 -> n_i parking -> h_new
#define OFF_WS   16384    // 2 x (128*36) weight slabs (double buffered)
#define OFF_BIDX 25600    // 64 ints
#define SMEM_FLOATS 25664
#define SMEM_BYTES (SMEM_FLOATS * 4)

#define WS_STRIDE 36
#define WS_SLABF  (128 * WS_STRIDE)   // 4608 floats per slab buffer

__device__ __forceinline__ int swz(int j) { return ((j >> 2) & 7) << 2; }

__device__ __forceinline__ float warp_sum(float v) {
#pragma unroll
    for (int o = 16; o > 0; o >>= 1) v += __shfl_xor_sync(0xffffffffu, v, o);
    return v;
}

// packed dual FMA: d.{lo,hi} += a.{lo,hi} * b.{lo,hi}
__device__ __forceinline__ void ffma2(ull& d, ull a, ull b) {
    asm("fma.rn.f32x2 %0, %1, %2, %0;" : "+l"(d) : "l"(a), "l"(b));
}
__device__ __forceinline__ float red2(ull v) {
    float lo = __uint_as_float((unsigned)(v & 0xffffffffull));
    float hi = __uint_as_float((unsigned)(v >> 32));
    return lo + hi;
}

#define CP_ASYNC16(dst_sm, src_gm) \
    asm volatile("cp.async.cg.shared.global [%0], [%1], 16;\n" :: "r"(dst_sm), "l"(src_gm))
#define CP_COMMIT() asm volatile("cp.async.commit_group;\n")
#define CP_WAIT1()  asm volatile("cp.async.wait_group 1;\n")
#define CP_WAIT0()  asm volatile("cp.async.wait_group 0;\n")

// slab s -> weight source pointer (already offset to k0), leading dim, rows
__device__ __forceinline__ const float* slab_src(int s, const float* W1, const float* Wih,
                                                 const float* Whh, const float* Wx,
                                                 int& ldW, int& rows) {
    if (s < 12) { ldW = 384; rows = 128; return W1 + s * 32; }
    if (s < 36) {
        int q = s - 12; int m = q >> 3; int half = (q >> 2) & 1; int k0 = (q & 3) * 32;
        ldW = 128; rows = 128;
        const float* base = half ? Whh : Wih;
        return base + m * 128 * 128 + k0;
    }
    ldW = 128; rows = 64; return Wx + (s - 36) * 32;
}

__device__ __forceinline__ void prefetch_slab(float* wsBuf, const float* Wsrc,
                                              int ldW, int rows, int t) {
    int total = rows * 8;  // 8 quads of 4 floats per row (32 k)
    for (int idx = t; idx < total; idx += THREADS) {
        int j = idx >> 3, kk = (idx & 7) * 4;
        unsigned dst = (unsigned)__cvta_generic_to_shared(wsBuf + j * WS_STRIDE + (kk ^ swz(j)));
        CP_ASYNC16(dst, Wsrc + j * ldW + kk);
    }
}

// A from smem plane (ld 128), warp's 8 rows; acc[8][4] packed over k-pairs
__device__ __forceinline__ void cs_smem(const float* __restrict__ Aplane, int k0,
                                        const float* __restrict__ Ws,
                                        int lane, int warp, ull acc[8][4]) {
    const float* Arow = Aplane + warp * 8 * 128 + k0;
    const float* Wj0 = Ws + (lane * 4 + 0) * WS_STRIDE;
    const float* Wj1 = Ws + (lane * 4 + 1) * WS_STRIDE;
    const float* Wj2 = Ws + (lane * 4 + 2) * WS_STRIDE;
    const float* Wj3 = Ws + (lane * 4 + 3) * WS_STRIDE;
    const int sw = swz(lane * 4);
#pragma unroll
    for (int kk = 0; kk < 32; kk += 4) {
        int kks = kk ^ sw;
        ulonglong2 w0 = *(const ulonglong2*)(Wj0 + kks);
        ulonglong2 w1 = *(const ulonglong2*)(Wj1 + kks);
        ulonglong2 w2 = *(const ulonglong2*)(Wj2 + kks);
        ulonglong2 w3 = *(const ulonglong2*)(Wj3 + kks);
#pragma unroll
        for (int ei = 0; ei < 8; ++ei) {
            ulonglong2 a = *(const ulonglong2*)(Arow + ei * 128 + kk);
            ffma2(acc[ei][0], a.x, w0.x); ffma2(acc[ei][0], a.y, w0.y);
            ffma2(acc[ei][1], a.x, w1.x); ffma2(acc[ei][1], a.y, w1.y);
            ffma2(acc[ei][2], a.x, w2.x); ffma2(acc[ei][2], a.y, w2.y);
            ffma2(acc[ei][3], a.x, w3.x); ffma2(acc[ei][3], a.y, w3.y);
        }
    }
}

// A rows from gmem (pre-offset pointers, 16B aligned)
__device__ __forceinline__ void cs_gmem(const float* const R[8],
                                        const float* __restrict__ Ws,
                                        int lane, ull acc[8][4]) {
    const float* Wj0 = Ws + (lane * 4 + 0) * WS_STRIDE;
    const float* Wj1 = Ws + (lane * 4 + 1) * WS_STRIDE;
    const float* Wj2 = Ws + (lane * 4 + 2) * WS_STRIDE;
    const float* Wj3 = Ws + (lane * 4 + 3) * WS_STRIDE;
    const int sw = swz(lane * 4);
#pragma unroll
    for (int kk = 0; kk < 32; kk += 4) {
        int kks = kk ^ sw;
        ulonglong2 w0 = *(const ulonglong2*)(Wj0 + kks);
        ulonglong2 w1 = *(const ulonglong2*)(Wj1 + kks);
        ulonglong2 w2 = *(const ulonglong2*)(Wj2 + kks);
        ulonglong2 w3 = *(const ulonglong2*)(Wj3 + kks);
#pragma unroll
        for (int ei = 0; ei < 8; ++ei) {
            ulonglong2 a = *(const ulonglong2*)(R[ei] + kk);
            ffma2(acc[ei][0], a.x, w0.x); ffma2(acc[ei][0], a.y, w0.y);
            ffma2(acc[ei][1], a.x, w1.x); ffma2(acc[ei][1], a.y, w1.y);
            ffma2(acc[ei][2], a.x, w2.x); ffma2(acc[ei][2], a.y, w2.y);
            ffma2(acc[ei][3], a.x, w3.x); ffma2(acc[ei][3], a.y, w3.y);
        }
    }
}

// GEMM3 variant: 2 j per lane (64 outputs), acc[8][2]
__device__ __forceinline__ void cs_smem2(const float* __restrict__ Aplane, int k0,
                                         const float* __restrict__ Ws,
                                         int lane, int warp, ull acc[8][2]) {
    const float* Arow = Aplane + warp * 8 * 128 + k0;
    const int j0 = lane * 2;
    const float* Wj0 = Ws + j0 * WS_STRIDE;
    const float* Wj1 = Ws + (j0 + 1) * WS_STRIDE;
    const int sw = swz(j0);
#pragma unroll
    for (int kk = 0; kk < 32; kk += 4) {
        int kks = kk ^ sw;
        ulonglong2 w0 = *(const ulonglong2*)(Wj0 + kks);
        ulonglong2 w1 = *(const ulonglong2*)(Wj1 + kks);
#pragma unroll
        for (int ei = 0; ei < 8; ++ei) {
            ulonglong2 a = *(const ulonglong2*)(Arow + ei * 128 + kk);
            ffma2(acc[ei][0], a.x, w0.x); ffma2(acc[ei][0], a.y, w0.y);
            ffma2(acc[ei][1], a.x, w1.x); ffma2(acc[ei][1], a.y, w1.y);
        }
    }
}

__global__ void __launch_bounds__(THREADS, 2)
edge_model_kernel(const float* __restrict__ src, const float* __restrict__ dest,
                  const float* __restrict__ edge_attr, const float* __restrict__ h,
                  const float* __restrict__ u, const int* __restrict__ batch,
                  const float* __restrict__ winding,
                  const float* __restrict__ Ww, const float* __restrict__ bw,
                  const float* __restrict__ gw, const float* __restrict__ betaw,
                  const float* __restrict__ W1, const float* __restrict__ b1,
                  const float* __restrict__ g1, const float* __restrict__ beta1,
                  const float* __restrict__ Wih, const float* __restrict__ Whh,
                  const float* __restrict__ bih, const float* __restrict__ bhh,
                  const float* __restrict__ Wx, const float* __restrict__ bx,
                  float* __restrict__ out_x, float* __restrict__ out_h, int E) {
    extern __shared__ float sm[];
    float* AW   = sm + OFF_AW;
    float* X1   = sm + OFF_X1;
    float* WsB  = sm + OFF_WS;
    int*   bidx = (int*)(sm + OFF_BIDX);

    const int t = threadIdx.x;
    const int warp = t >> 5, lane = t & 31;
    const int eb = blockIdx.x * TILE;
    const int e0 = eb + warp * 8;

#define PREFETCH(sn) do { int ldW_, rows_; \
    const float* ws_ = slab_src((sn), W1, Wih, Whh, Wx, ldW_, rows_); \
    prefetch_slab(WsB + ((sn) & 1) * WS_SLABF, ws_, ldW_, rows_, t); CP_COMMIT(); } while (0)

    // start weight pipeline
    PREFETCH(0);

    // batch indices for u gather (used at GEMM1 slabs 6-7; barriers before then)
    if (t < TILE) { int ge = eb + t; bidx[t] = (ge < E) ? batch[ge] : 0; }

    // ---- winding mlp: Linear(2->128) + LN + ReLU -> AW (warp-private rows) ----
    {
        float wa[4], wb[4], bwv[4], gwv[4], bev[4];
#pragma unroll
        for (int q = 0; q < 4; ++q) {
            int jj = lane + q * 32;
            wa[q] = __ldg(Ww + jj * 2); wb[q] = __ldg(Ww + jj * 2 + 1);
            bwv[q] = __ldg(bw + jj); gwv[q] = __ldg(gw + jj); bev[q] = __ldg(betaw + jj);
        }
#pragma unroll
        for (int ei = 0; ei < 8; ++ei) {
            int e = warp * 8 + ei, ge = eb + e;
            float wd0 = 0.f, wd1 = 0.f;
            if (ge < E) { wd0 = winding[(size_t)ge * 2]; wd1 = winding[(size_t)ge * 2 + 1]; }
            float v[4], s = 0.f, s2 = 0.f;
#pragma unroll
            for (int q = 0; q < 4; ++q) {
                float p = fmaf(wd0, wa[q], fmaf(wd1, wb[q], bwv[q]));
                v[q] = p; s += p; s2 += p * p;
            }
            s = warp_sum(s); s2 = warp_sum(s2);
            float mu = s * (1.f / 128.f);
            float var = fmaxf(s2 * (1.f / 128.f) - mu * mu, 0.f);
            float rs = rsqrtf(var + 1e-5f);
#pragma unroll
            for (int q = 0; q < 4; ++q)
                AW[e * 128 + lane + q * 32] = fmaxf((v[q] - mu) * rs * gwv[q] + bev[q], 0.f);
        }
    }

    // ---------------- GEMM1: P = [src|dest|ea|u|w] @ W1^T (12 slabs) ----------------
    {
        ull acc[8][4];
#pragma unroll
        for (int a_ = 0; a_ < 8; ++a_)
#pragma unroll
            for (int b_ = 0; b_ < 4; ++b_) acc[a_][b_] = 0ull;
#pragma unroll 1
        for (int s = 0; s < 12; ++s) {
            PREFETCH(s + 1);
            CP_WAIT1();
            __syncthreads();
            const float* Wsb = WsB + (s & 1) * WS_SLABF;
            if (s < 8) {
                const float* R[8];
                if (s < 6) {
                    const float* base = (s < 2) ? src : (s < 4) ? dest : edge_attr;
                    int k0 = (s & 1) * 32;
#pragma unroll
                    for (int ei = 0; ei < 8; ++ei) {
                        int ge = e0 + ei; if (ge > E - 1) ge = E - 1;
                        R[ei] = base + (size_t)ge * 64 + k0;
                    }
                } else {
                    int k0 = (s - 6) * 32;
#pragma unroll
                    for (int ei = 0; ei < 8; ++ei)
                        R[ei] = u + bidx[warp * 8 + ei] * 64 + k0;
                }
                cs_gmem(R, Wsb, lane, acc);
            } else {
                cs_smem(AW, (s - 8) * 32, Wsb, lane, warp, acc);
            }
            __syncthreads();
        }
        float4 bq = __ldg((const float4*)(b1 + lane * 4));
#pragma unroll
        for (int ei = 0; ei < 8; ++ei)
            *(float4*)(X1 + (warp * 8 + ei) * 128 + lane * 4) =
                make_float4(red2(acc[ei][0]) + bq.x, red2(acc[ei][1]) + bq.y,
                            red2(acc[ei][2]) + bq.z, red2(acc[ei][3]) + bq.w);
    }
    __syncwarp();
    // LN + ReLU in place (rows are warp-private)
    {
        float g1v[4], be1v[4];
#pragma unroll
        for (int q = 0; q < 4; ++q) {
            int jj = lane + q * 32;
            g1v[q] = __ldg(g1 + jj); be1v[q] = __ldg(beta1 + jj);
        }
#pragma unroll
        for (int ei = 0; ei < 8; ++ei) {
            int e = warp * 8 + ei;
            float v[4], s = 0.f, s2 = 0.f;
#pragma unroll
            for (int q = 0; q < 4; ++q) {
                float p = X1[e * 128 + lane + q * 32];
                v[q] = p; s += p; s2 += p * p;
            }
            s = warp_sum(s); s2 = warp_sum(s2);
            float mu = s * (1.f / 128.f);
            float var = fmaxf(s2 * (1.f / 128.f) - mu * mu, 0.f);
            float rs = rsqrtf(var + 1e-5f);
#pragma unroll
            for (int q = 0; q < 4; ++q)
                X1[e * 128 + lane + q * 32] = fmaxf((v[q] - mu) * rs * g1v[q] + be1v[q], 0.f);
        }
    }
    __syncwarp();

    // ---------------- GEMM2: r gate (->AW) and z gate (->regs) ----------------
    float zg[8][4];
#pragma unroll 1
    for (int m = 0; m < 2; ++m) {
        ull acc[8][4];
#pragma unroll
        for (int a_ = 0; a_ < 8; ++a_)
#pragma unroll
            for (int b_ = 0; b_ < 4; ++b_) acc[a_][b_] = 0ull;
#pragma unroll 1
        for (int ss = 0; ss < 8; ++ss) {
            int s = 12 + m * 8 + ss;
            PREFETCH(s + 1);
            CP_WAIT1();
            __syncthreads();
            const float* Wsb = WsB + (s & 1) * WS_SLABF;
            if (ss < 4) cs_smem(X1, ss * 32, Wsb, lane, warp, acc);
            else {
                const float* R[8];
                int k0 = (ss - 4) * 32;
#pragma unroll
                for (int ei = 0; ei < 8; ++ei) {
                    int ge = e0 + ei; if (ge > E - 1) ge = E - 1;
                    R[ei] = h + (size_t)ge * 128 + k0;
                }
                cs_gmem(R, Wsb, lane, acc);
            }
            __syncthreads();
        }
        float4 biq = __ldg((const float4*)(bih + m * 128 + lane * 4));
        float4 bhq = __ldg((const float4*)(bhh + m * 128 + lane * 4));
#pragma unroll
        for (int ei = 0; ei < 8; ++ei) {
            float g0 = 1.f / (1.f + expf(-(red2(acc[ei][0]) + biq.x + bhq.x)));
            float g1_ = 1.f / (1.f + expf(-(red2(acc[ei][1]) + biq.y + bhq.y)));
            float g2 = 1.f / (1.f + expf(-(red2(acc[ei][2]) + biq.z + bhq.z)));
            float g3 = 1.f / (1.f + expf(-(red2(acc[ei][3]) + biq.w + bhq.w)));
            if (m == 0)
                *(float4*)(AW + (warp * 8 + ei) * 128 + lane * 4) = make_float4(g0, g1_, g2, g3);
            else { zg[ei][0] = g0; zg[ei][1] = g1_; zg[ei][2] = g2; zg[ei][3] = g3; }
        }
    }

    // ---------------- GEMM2: n gate (i-pass -> park in X1, then h-pass) ----------------
    {
        ull acc[8][4];
#pragma unroll
        for (int a_ = 0; a_ < 8; ++a_)
#pragma unroll
            for (int b_ = 0; b_ < 4; ++b_) acc[a_][b_] = 0ull;
#pragma unroll 1
        for (int ss = 0; ss < 4; ++ss) {
            int s = 28 + ss;
            PREFETCH(s + 1);
            CP_WAIT1();
            __syncthreads();
            cs_smem(X1, ss * 32, WsB + (s & 1) * WS_SLABF, lane, warp, acc);
            __syncthreads();
        }
        // park i_n + bih into X1 (all warps finished reading X1; rows/cols are thread-private)
        {
            float4 biq = __ldg((const float4*)(bih + 256 + lane * 4));
#pragma unroll
            for (int ei = 0; ei < 8; ++ei)
                *(float4*)(X1 + (warp * 8 + ei) * 128 + lane * 4) =
                    make_float4(red2(acc[ei][0]) + biq.x, red2(acc[ei][1]) + biq.y,
                                red2(acc[ei][2]) + biq.z, red2(acc[ei][3]) + biq.w);
        }
#pragma unroll
        for (int a_ = 0; a_ < 8; ++a_)
#pragma unroll
            for (int b_ = 0; b_ < 4; ++b_) acc[a_][b_] = 0ull;
#pragma unroll 1
        for (int ss = 4; ss < 8; ++ss) {
            int s = 28 + ss;
            PREFETCH(s + 1);
            CP_WAIT1();
            __syncthreads();
            const float* R[8];
            int k0 = (ss - 4) * 32;
#pragma unroll
            for (int ei = 0; ei < 8; ++ei) {
                int ge = e0 + ei; if (ge > E - 1) ge = E - 1;
                R[ei] = h + (size_t)ge * 128 + k0;
            }
            cs_gmem(R, WsB + (s & 1) * WS_SLABF, lane, acc);
            __syncthreads();
        }
        // combine: n = tanh(i_n + r*(h_n)); h_new = (1-z)*n + z*h
        float4 bhq = __ldg((const float4*)(bhh + 256 + lane * 4));
#pragma unroll
        for (int ei = 0; ei < 8; ++ei) {
            int ge = e0 + ei; int geC = (ge > E - 1) ? E - 1 : ge;
            float4 hv = __ldg((const float4*)(h + (size_t)geC * 128 + lane * 4));
            float4 ni = *(const float4*)(X1 + (warp * 8 + ei) * 128 + lane * 4);
            float4 rv = *(const float4*)(AW + (warp * 8 + ei) * 128 + lane * 4);
            float n0 = tanhf(ni.x + rv.x * (red2(acc[ei][0]) + bhq.x));
            float n1 = tanhf(ni.y + rv.y * (red2(acc[ei][1]) + bhq.y));
            float n2 = tanhf(ni.z + rv.z * (red2(acc[ei][2]) + bhq.z));
            float n3 = tanhf(ni.w + rv.w * (red2(acc[ei][3]) + bhq.w));
            float4 hn;
            hn.x = (1.f - zg[ei][0]) * n0 + zg[ei][0] * hv.x;
            hn.y = (1.f - zg[ei][1]) * n1 + zg[ei][1] * hv.y;
            hn.z = (1.f - zg[ei][2]) * n2 + zg[ei][2] * hv.z;
            hn.w = (1.f - zg[ei][3]) * n3 + zg[ei][3] * hv.w;
            if (ge < E) *(float4*)(out_h + (size_t)ge * 128 + lane * 4) = hn;
            *(float4*)(X1 + (warp * 8 + ei) * 128 + lane * 4) = hn;  // for GEMM3
        }
    }

    // ---------------- GEMM3: x_out = h_new @ Wx^T (4 slabs, 8e x 2j) ----------------
    {
        ull acc3[8][2];
#pragma unroll
        for (int a_ = 0; a_ < 8; ++a_) { acc3[a_][0] = 0ull; acc3[a_][1] = 0ull; }
#pragma unroll 1
        for (int ss = 0; ss < 4; ++ss) {
            int s = 36 + ss;
            if (s + 1 < 40) { PREFETCH(s + 1); CP_WAIT1(); }
            else CP_WAIT0();
            __syncthreads();
            cs_smem2(X1, ss * 32, WsB + (s & 1) * WS_SLABF, lane, warp, acc3);
            __syncthreads();
        }
        float bx0 = __ldg(bx + lane * 2), bx1 = __ldg(bx + lane * 2 + 1);
#pragma unroll
        for (int ei = 0; ei < 8; ++ei) {
            int ge = e0 + ei;
            if (ge < E)
                *(float2*)(out_x + (size_t)ge * 64 + lane * 2) =
                    make_float2(red2(acc3[ei][0]) + bx0, red2(acc3[ei][1]) + bx1);
        }
    }
#undef PREFETCH
}

extern "C" void kernel_launch(void* const* d_in, const int* in_sizes, int n_in,
                              void* d_out, int out_size) {
    const float* src       = (const float*)d_in[0];
    const float* dest      = (const float*)d_in[1];
    const float* edge_attr = (const float*)d_in[2];
    const float* h         = (const float*)d_in[3];
    const float* u         = (const float*)d_in[4];
    const int*   batch     = (const int*)d_in[5];
    const float* winding   = (const float*)d_in[6];
    const float* Ww        = (const float*)d_in[7];
    const float* bw        = (const float*)d_in[8];
    const float* gw        = (const float*)d_in[9];
    const float* betaw     = (const float*)d_in[10];
    const float* W1        = (const float*)d_in[11];
    const float* b1        = (const float*)d_in[12];
    const float* g1        = (const float*)d_in[13];
    const float* beta1     = (const float*)d_in[14];
    const float* Wih       = (const float*)d_in[15];
    const float* Whh       = (const float*)d_in[16];
    const float* bih       = (const float*)d_in[17];
    const float* bhh       = (const float*)d_in[18];
    const float* Wx        = (const float*)d_in[19];
    const float* bx        = (const float*)d_in[20];

    const int E = in_sizes[0] / 64;  // src is [E, 64]
    float* out_x = (float*)d_out;              // [E, 64]
    float* out_h = out_x + (size_t)E * 64;     // [E, 128]

    cudaFuncSetAttribute(edge_model_kernel,
                         cudaFuncAttributeMaxDynamicSharedMemorySize, SMEM_BYTES);

    int blocks = (E + TILE - 1) / TILE;
    edge_model_kernel<<<blocks, THREADS, SMEM_BYTES>>>(
        src, dest, edge_attr, h, u, batch, winding,
        Ww, bw, gw, betaw, W1, b1, g1, beta1,
        Wih, Whh, bih, bhh, Wx, bx, out_x, out_h, E);
}

// round 17
// speedup vs baseline: 2.4101x; 1.0876x over previous
#include <cuda_runtime.h>
#include <math.h>

#define THREADS 256
#define TILE 64
#define NSLABS 40

typedef unsigned long long ull;

// ---- shared memory layout (floats) ----
// X1 is multi-use, all rows warp-private: winding-out -> x1 -> n_i park -> h_new
#define OFF_X1   0        // 64 x 128
#define OFF_WS   8192     // 3 x (128*36) weight slab ring
#define OFF_BIDX 22016    // 64 ints
#define SMEM_FLOATS 22080
#define SMEM_BYTES (SMEM_FLOATS * 4)

#define WS_STRIDE 36
#define WS_SLABF  (128 * WS_STRIDE)   // 4608 floats per slab buffer

__device__ __forceinline__ int swz(int j) { return ((j >> 2) & 7) << 2; }

__device__ __forceinline__ float warp_sum(float v) {
#pragma unroll
    for (int o = 16; o > 0; o >>= 1) v += __shfl_xor_sync(0xffffffffu, v, o);
    return v;
}

__device__ __forceinline__ void ffma2(ull& d, ull a, ull b) {
    asm("fma.rn.f32x2 %0, %1, %2, %0;" : "+l"(d) : "l"(a), "l"(b));
}
__device__ __forceinline__ float red2(ull v) {
    float lo = __uint_as_float((unsigned)(v & 0xffffffffull));
    float hi = __uint_as_float((unsigned)(v >> 32));
    return lo + hi;
}

__device__ __forceinline__ float sigmoid_f(float x) {
    return __fdividef(1.f, 1.f + __expf(-x));
}
__device__ __forceinline__ float tanh_f(float x) {
    return 1.f - __fdividef(2.f, __expf(2.f * x) + 1.f);
}

#define CP_ASYNC16(dst_sm, src_gm) \
    asm volatile("cp.async.cg.shared.global [%0], [%1], 16;\n" :: "r"(dst_sm), "l"(src_gm))
#define CP_COMMIT() asm volatile("cp.async.commit_group;\n")
#define CP_WAIT2()  asm volatile("cp.async.wait_group 2;\n")
#define CP_WAIT1()  asm volatile("cp.async.wait_group 1;\n")
#define CP_WAIT0()  asm volatile("cp.async.wait_group 0;\n")

// slab s -> weight source pointer (already offset to k0), leading dim, rows
__device__ __forceinline__ const float* slab_src(int s, const float* W1, const float* Wih,
                                                 const float* Whh, const float* Wx,
                                                 int& ldW, int& rows) {
    if (s < 12) { ldW = 384; rows = 128; return W1 + s * 32; }
    if (s < 36) {
        int q = s - 12; int m = q >> 3; int half = (q >> 2) & 1; int k0 = (q & 3) * 32;
        ldW = 128; rows = 128;
        const float* base = half ? Whh : Wih;
        return base + m * 128 * 128 + k0;
    }
    ldW = 128; rows = 64; return Wx + (s - 36) * 32;
}

__device__ __forceinline__ void prefetch_slab(float* wsBuf, const float* Wsrc,
                                              int ldW, int rows, int t) {
    int total = rows * 8;
    for (int idx = t; idx < total; idx += THREADS) {
        int j = idx >> 3, kk = (idx & 7) * 4;
        unsigned dst = (unsigned)__cvta_generic_to_shared(wsBuf + j * WS_STRIDE + (kk ^ swz(j)));
        CP_ASYNC16(dst, Wsrc + j * ldW + kk);
    }
}

// A from smem plane (ld 128), warp's 8 rows; acc[8][4] packed over k-pairs
__device__ __forceinline__ void cs_smem(const float* __restrict__ Aplane, int k0,
                                        const float* __restrict__ Ws,
                                        int lane, int warp, ull acc[8][4]) {
    const float* Arow = Aplane + warp * 8 * 128 + k0;
    const float* Wj0 = Ws + (lane * 4 + 0) * WS_STRIDE;
    const float* Wj1 = Ws + (lane * 4 + 1) * WS_STRIDE;
    const float* Wj2 = Ws + (lane * 4 + 2) * WS_STRIDE;
    const float* Wj3 = Ws + (lane * 4 + 3) * WS_STRIDE;
    const int sw = swz(lane * 4);
#pragma unroll
    for (int kk = 0; kk < 32; kk += 4) {
        int kks = kk ^ sw;
        ulonglong2 w0 = *(const ulonglong2*)(Wj0 + kks);
        ulonglong2 w1 = *(const ulonglong2*)(Wj1 + kks);
        ulonglong2 w2 = *(const ulonglong2*)(Wj2 + kks);
        ulonglong2 w3 = *(const ulonglong2*)(Wj3 + kks);
#pragma unroll
        for (int ei = 0; ei < 8; ++ei) {
            ulonglong2 a = *(const ulonglong2*)(Arow + ei * 128 + kk);
            ffma2(acc[ei][0], a.x, w0.x); ffma2(acc[ei][0], a.y, w0.y);
            ffma2(acc[ei][1], a.x, w1.x); ffma2(acc[ei][1], a.y, w1.y);
            ffma2(acc[ei][2], a.x, w2.x); ffma2(acc[ei][2], a.y, w2.y);
            ffma2(acc[ei][3], a.x, w3.x); ffma2(acc[ei][3], a.y, w3.y);
        }
    }
}

// A rows from gmem (pre-offset pointers, 16B aligned)
__device__ __forceinline__ void cs_gmem(const float* const R[8],
                                        const float* __restrict__ Ws,
                                        int lane, ull acc[8][4]) {
    const float* Wj0 = Ws + (lane * 4 + 0) * WS_STRIDE;
    const float* Wj1 = Ws + (lane * 4 + 1) * WS_STRIDE;
    const float* Wj2 = Ws + (lane * 4 + 2) * WS_STRIDE;
    const float* Wj3 = Ws + (lane * 4 + 3) * WS_STRIDE;
    const int sw = swz(lane * 4);
#pragma unroll
    for (int kk = 0; kk < 32; kk += 4) {
        int kks = kk ^ sw;
        ulonglong2 w0 = *(const ulonglong2*)(Wj0 + kks);
        ulonglong2 w1 = *(const ulonglong2*)(Wj1 + kks);
        ulonglong2 w2 = *(const ulonglong2*)(Wj2 + kks);
        ulonglong2 w3 = *(const ulonglong2*)(Wj3 + kks);
#pragma unroll
        for (int ei = 0; ei < 8; ++ei) {
            ulonglong2 a = *(const ulonglong2*)(R[ei] + kk);
            ffma2(acc[ei][0], a.x, w0.x); ffma2(acc[ei][0], a.y, w0.y);
            ffma2(acc[ei][1], a.x, w1.x); ffma2(acc[ei][1], a.y, w1.y);
            ffma2(acc[ei][2], a.x, w2.x); ffma2(acc[ei][2], a.y, w2.y);
            ffma2(acc[ei][3], a.x, w3.x); ffma2(acc[ei][3], a.y, w3.y);
        }
    }
}

// GEMM3 variant: 2 j per lane (64 outputs), acc[8][2]
__device__ __forceinline__ void cs_smem2(const float* __restrict__ Aplane, int k0,
                                         const float* __restrict__ Ws,
                                         int lane, int warp, ull acc[8][2]) {
    const float* Arow = Aplane + warp * 8 * 128 + k0;
    const int j0 = lane * 2;
    const float* Wj0 = Ws + j0 * WS_STRIDE;
    const float* Wj1 = Ws + (j0 + 1) * WS_STRIDE;
    const int sw = swz(j0);
#pragma unroll
    for (int kk = 0; kk < 32; kk += 4) {
        int kks = kk ^ sw;
        ulonglong2 w0 = *(const ulonglong2*)(Wj0 + kks);
        ulonglong2 w1 = *(const ulonglong2*)(Wj1 + kks);
#pragma unroll
        for (int ei = 0; ei < 8; ++ei) {
            ulonglong2 a = *(const ulonglong2*)(Arow + ei * 128 + kk);
            ffma2(acc[ei][0], a.x, w0.x); ffma2(acc[ei][0], a.y, w0.y);
            ffma2(acc[ei][1], a.x, w1.x); ffma2(acc[ei][1], a.y, w1.y);
        }
    }
}

__global__ void __launch_bounds__(THREADS, 2)
edge_model_kernel(const float* __restrict__ src, const float* __restrict__ dest,
                  const float* __restrict__ edge_attr, const float* __restrict__ h,
                  const float* __restrict__ u, const int* __restrict__ batch,
                  const float* __restrict__ winding,
                  const float* __restrict__ Ww, const float* __restrict__ bw,
                  const float* __restrict__ gw, const float* __restrict__ betaw,
                  const float* __restrict__ W1, const float* __restrict__ b1,
                  const float* __restrict__ g1, const float* __restrict__ beta1,
                  const float* __restrict__ Wih, const float* __restrict__ Whh,
                  const float* __restrict__ bih, const float* __restrict__ bhh,
                  const float* __restrict__ Wx, const float* __restrict__ bx,
                  float* __restrict__ out_x, float* __restrict__ out_h, int E) {
    extern __shared__ float sm[];
    float* X1   = sm + OFF_X1;
    float* WsB  = sm + OFF_WS;
    int*   bidx = (int*)(sm + OFF_BIDX);

    const int t = threadIdx.x;
    const int warp = t >> 5, lane = t & 31;
    const int eb = blockIdx.x * TILE;
    const int e0 = eb + warp * 8;

#define PREFETCH(sn) do { int ldW_, rows_; \
    const float* ws_ = slab_src((sn), W1, Wih, Whh, Wx, ldW_, rows_); \
    prefetch_slab(WsB + ((sn) % 3) * WS_SLABF, ws_, ldW_, rows_, t); CP_COMMIT(); } while (0)

// one barrier per slab; 3-stage ring; commit s+2, ensure slab s arrived
#define PIPE_STEP(s) do { \
    __syncthreads(); \
    if ((s) + 2 < NSLABS) PREFETCH((s) + 2); \
    if ((s) <= NSLABS - 3) CP_WAIT2(); \
    else if ((s) == NSLABS - 2) CP_WAIT1(); \
    else CP_WAIT0(); \
} while (0)

    // warm pipeline: slabs 0 and 1 in flight
    PREFETCH(0);
    PREFETCH(1);

    if (t < TILE) { int ge = eb + t; bidx[t] = (ge < E) ? batch[ge] : 0; }

    // ---- winding mlp: Linear(2->128) + LN + ReLU -> X1 (warp-private rows) ----
    {
        float wa[4], wb[4], bwv[4], gwv[4], bev[4];
#pragma unroll
        for (int q = 0; q < 4; ++q) {
            int jj = lane + q * 32;
            wa[q] = __ldg(Ww + jj * 2); wb[q] = __ldg(Ww + jj * 2 + 1);
            bwv[q] = __ldg(bw + jj); gwv[q] = __ldg(gw + jj); bev[q] = __ldg(betaw + jj);
        }
#pragma unroll
        for (int ei = 0; ei < 8; ++ei) {
            int e = warp * 8 + ei, ge = eb + e;
            float wd0 = 0.f, wd1 = 0.f;
            if (ge < E) { wd0 = winding[(size_t)ge * 2]; wd1 = winding[(size_t)ge * 2 + 1]; }
            float v[4], s = 0.f, s2 = 0.f;
#pragma unroll
            for (int q = 0; q < 4; ++q) {
                float p = fmaf(wd0, wa[q], fmaf(wd1, wb[q], bwv[q]));
                v[q] = p; s += p; s2 += p * p;
            }
            s = warp_sum(s); s2 = warp_sum(s2);
            float mu = s * (1.f / 128.f);
            float var = fmaxf(s2 * (1.f / 128.f) - mu * mu, 0.f);
            float rs = rsqrtf(var + 1e-5f);
#pragma unroll
            for (int q = 0; q < 4; ++q)
                X1[e * 128 + lane + q * 32] = fmaxf((v[q] - mu) * rs * gwv[q] + bev[q], 0.f);
        }
    }

    // ---------------- GEMM1: P = [src|dest|ea|u|winding-out] @ W1^T (slabs 0-11) --------
    {
        ull acc[8][4];
#pragma unroll
        for (int a_ = 0; a_ < 8; ++a_)
#pragma unroll
            for (int b_ = 0; b_ < 4; ++b_) acc[a_][b_] = 0ull;
#pragma unroll 1
        for (int s = 0; s < 12; ++s) {
            PIPE_STEP(s);
            const float* Wsb = WsB + (s % 3) * WS_SLABF;
            if (s < 8) {
                const float* R[8];
                if (s < 6) {
                    const float* base = (s < 2) ? src : (s < 4) ? dest : edge_attr;
                    int k0 = (s & 1) * 32;
#pragma unroll
                    for (int ei = 0; ei < 8; ++ei) {
                        int ge = e0 + ei; if (ge > E - 1) ge = E - 1;
                        R[ei] = base + (size_t)ge * 64 + k0;
                    }
                } else {
                    int k0 = (s - 6) * 32;
#pragma unroll
                    for (int ei = 0; ei < 8; ++ei)
                        R[ei] = u + bidx[warp * 8 + ei] * 64 + k0;
                }
                cs_gmem(R, Wsb, lane, acc);
            } else {
                cs_smem(X1, (s - 8) * 32, Wsb, lane, warp, acc);  // winding-out
            }
        }
        __syncwarp();
        float4 bq = __ldg((const float4*)(b1 + lane * 4));
#pragma unroll
        for (int ei = 0; ei < 8; ++ei)
            *(float4*)(X1 + (warp * 8 + ei) * 128 + lane * 4) =
                make_float4(red2(acc[ei][0]) + bq.x, red2(acc[ei][1]) + bq.y,
                            red2(acc[ei][2]) + bq.z, red2(acc[ei][3]) + bq.w);
    }
    __syncwarp();
    // LN + ReLU in place (rows warp-private)
    {
        float g1v[4], be1v[4];
#pragma unroll
        for (int q = 0; q < 4; ++q) {
            int jj = lane + q * 32;
            g1v[q] = __ldg(g1 + jj); be1v[q] = __ldg(beta1 + jj);
        }
#pragma unroll
        for (int ei = 0; ei < 8; ++ei) {
            int e = warp * 8 + ei;
            float v[4], s = 0.f, s2 = 0.f;
#pragma unroll
            for (int q = 0; q < 4; ++q) {
                float p = X1[e * 128 + lane + q * 32];
                v[q] = p; s += p; s2 += p * p;
            }
            s = warp_sum(s); s2 = warp_sum(s2);
            float mu = s * (1.f / 128.f);
            float var = fmaxf(s2 * (1.f / 128.f) - mu * mu, 0.f);
            float rs = rsqrtf(var + 1e-5f);
#pragma unroll
            for (int q = 0; q < 4; ++q)
                X1[e * 128 + lane + q * 32] = fmaxf((v[q] - mu) * rs * g1v[q] + be1v[q], 0.f);
        }
    }
    __syncwarp();

    // ---------------- GEMM2: r gate (-> out_h scratch) and z gate (-> regs) ----------
    float zg[8][4];
#pragma unroll 1
    for (int m = 0; m < 2; ++m) {
        ull acc[8][4];
#pragma unroll
        for (int a_ = 0; a_ < 8; ++a_)
#pragma unroll
            for (int b_ = 0; b_ < 4; ++b_) acc[a_][b_] = 0ull;
#pragma unroll 1
        for (int ss = 0; ss < 8; ++ss) {
            int s = 12 + m * 8 + ss;
            PIPE_STEP(s);
            const float* Wsb = WsB + (s % 3) * WS_SLABF;
            if (ss < 4) cs_smem(X1, ss * 32, Wsb, lane, warp, acc);
            else {
                const float* R[8];
                int k0 = (ss - 4) * 32;
#pragma unroll
                for (int ei = 0; ei < 8; ++ei) {
                    int ge = e0 + ei; if (ge > E - 1) ge = E - 1;
                    R[ei] = h + (size_t)ge * 128 + k0;
                }
                cs_gmem(R, Wsb, lane, acc);
            }
        }
        float4 biq = __ldg((const float4*)(bih + m * 128 + lane * 4));
        float4 bhq = __ldg((const float4*)(bhh + m * 128 + lane * 4));
#pragma unroll
        for (int ei = 0; ei < 8; ++ei) {
            float g0 = sigmoid_f(red2(acc[ei][0]) + biq.x + bhq.x);
            float g1_ = sigmoid_f(red2(acc[ei][1]) + biq.y + bhq.y);
            float g2 = sigmoid_f(red2(acc[ei][2]) + biq.z + bhq.z);
            float g3 = sigmoid_f(red2(acc[ei][3]) + biq.w + bhq.w);
            if (m == 0) {
                int ge = e0 + ei;
                if (ge < E)  // park r in out_h scratch (overwritten by h_new later)
                    *(float4*)(out_h + (size_t)ge * 128 + lane * 4) = make_float4(g0, g1_, g2, g3);
            } else { zg[ei][0] = g0; zg[ei][1] = g1_; zg[ei][2] = g2; zg[ei][3] = g3; }
        }
    }

    // ---------------- GEMM2: n gate (i-pass -> park in X1, then h-pass) -------------
    {
        ull acc[8][4];
#pragma unroll
        for (int a_ = 0; a_ < 8; ++a_)
#pragma unroll
            for (int b_ = 0; b_ < 4; ++b_) acc[a_][b_] = 0ull;
#pragma unroll 1
        for (int ss = 0; ss < 4; ++ss) {
            int s = 28 + ss;
            PIPE_STEP(s);
            cs_smem(X1, ss * 32, WsB + (s % 3) * WS_SLABF, lane, warp, acc);
        }
        // park i_n + bih into X1 (own rows/cols; x1 no longer needed by this warp)
        {
            float4 biq = __ldg((const float4*)(bih + 256 + lane * 4));
#pragma unroll
            for (int ei = 0; ei < 8; ++ei)
                *(float4*)(X1 + (warp * 8 + ei) * 128 + lane * 4) =
                    make_float4(red2(acc[ei][0]) + biq.x, red2(acc[ei][1]) + biq.y,
                                red2(acc[ei][2]) + biq.z, red2(acc[ei][3]) + biq.w);
        }
#pragma unroll
        for (int a_ = 0; a_ < 8; ++a_)
#pragma unroll
            for (int b_ = 0; b_ < 4; ++b_) acc[a_][b_] = 0ull;
#pragma unroll 1
        for (int ss = 4; ss < 8; ++ss) {
            int s = 28 + ss;
            PIPE_STEP(s);
            const float* R[8];
            int k0 = (ss - 4) * 32;
#pragma unroll
            for (int ei = 0; ei < 8; ++ei) {
                int ge = e0 + ei; if (ge > E - 1) ge = E - 1;
                R[ei] = h + (size_t)ge * 128 + k0;
            }
            cs_gmem(R, WsB + (s % 3) * WS_SLABF, lane, acc);
        }
        // combine: n = tanh(i_n + r*h_n); h_new = (1-z)*n + z*h
        float4 bhq = __ldg((const float4*)(bhh + 256 + lane * 4));
#pragma unroll
        for (int ei = 0; ei < 8; ++ei) {
            int ge = e0 + ei; int geC = (ge > E - 1) ? E - 1 : ge;
            float4 hv = __ldg((const float4*)(h + (size_t)geC * 128 + lane * 4));
            float4 ni = *(const float4*)(X1 + (warp * 8 + ei) * 128 + lane * 4);
            float4 rv = *(const float4*)(out_h + (size_t)geC * 128 + lane * 4);
            float n0 = tanh_f(ni.x + rv.x * (red2(acc[ei][0]) + bhq.x));
            float n1 = tanh_f(ni.y + rv.y * (red2(acc[ei][1]) + bhq.y));
            float n2 = tanh_f(ni.z + rv.z * (red2(acc[ei][2]) + bhq.z));
            float n3 = tanh_f(ni.w + rv.w * (red2(acc[ei][3]) + bhq.w));
            float4 hn;
            hn.x = (1.f - zg[ei][0]) * n0 + zg[ei][0] * hv.x;
            hn.y = (1.f - zg[ei][1]) * n1 + zg[ei][1] * hv.y;
            hn.z = (1.f - zg[ei][2]) * n2 + zg[ei][2] * hv.z;
            hn.w = (1.f - zg[ei][3]) * n3 + zg[ei][3] * hv.w;
            if (ge < E) *(float4*)(out_h + (size_t)ge * 128 + lane * 4) = hn;
            *(float4*)(X1 + (warp * 8 + ei) * 128 + lane * 4) = hn;  // for GEMM3
        }
    }

    // ---------------- GEMM3: x_out = h_new @ Wx^T (slabs 36-39, 8e x 2j) -------------
    {
        ull acc3[8][2];
#pragma unroll
        for (int a_ = 0; a_ < 8; ++a_) { acc3[a_][0] = 0ull; acc3[a_][1] = 0ull; }
#pragma unroll 1
        for (int ss = 0; ss < 4; ++ss) {
            int s = 36 + ss;
            PIPE_STEP(s);
            cs_smem2(X1, ss * 32, WsB + (s % 3) * WS_SLABF, lane, warp, acc3);
        }
        float bx0 = __ldg(bx + lane * 2), bx1 = __ldg(bx + lane * 2 + 1);
#pragma unroll
        for (int ei = 0; ei < 8; ++ei) {
            int ge = e0 + ei;
            if (ge < E)
                *(float2*)(out_x + (size_t)ge * 64 + lane * 2) =
                    make_float2(red2(acc3[ei][0]) + bx0, red2(acc3[ei][1]) + bx1);
        }
    }
#undef PIPE_STEP
#undef PREFETCH
}

extern "C" void kernel_launch(void* const* d_in, const int* in_sizes, int n_in,
                              void* d_out, int out_size) {
    const float* src       = (const float*)d_in[0];
    const float* dest      = (const float*)d_in[1];
    const float* edge_attr = (const float*)d_in[2];
    const float* h         = (const float*)d_in[3];
    const float* u         = (const float*)d_in[4];
    const int*   batch     = (const int*)d_in[5];
    const float* winding   = (const float*)d_in[6];
    const float* Ww        = (const float*)d_in[7];
    const float* bw        = (const float*)d_in[8];
    const float* gw        = (const float*)d_in[9];
    const float* betaw     = (const float*)d_in[10];
    const float* W1        = (const float*)d_in[11];
    const float* b1        = (const float*)d_in[12];
    const float* g1        = (const float*)d_in[13];
    const float* beta1     = (const float*)d_in[14];
    const float* Wih       = (const float*)d_in[15];
    const float* Whh       = (const float*)d_in[16];
    const float* bih       = (const float*)d_in[17];
    const float* bhh       = (const float*)d_in[18];
    const float* Wx        = (const float*)d_in[19];
    const float* bx        = (const float*)d_in[20];

    const int E = in_sizes[0] / 64;  // src is [E, 64]
    float* out_x = (float*)d_out;              // [E, 64]
    float* out_h = out_x + (size_t)E * 64;     // [E, 128]

    cudaFuncSetAttribute(edge_model_kernel,
                         cudaFuncAttributeMaxDynamicSharedMemorySize, SMEM_BYTES);

    int blocks = (E + TILE - 1) / TILE;
    edge_model_kernel<<<blocks, THREADS, SMEM_BYTES>>>(
        src, dest, edge_attr, h, u, batch, winding,
        Ww, bw, gw, betaw, W1, b1, g1, beta1,
        Wih, Whh, bih, bhh, Wx, bx, out_x, out_h, E);
}